// round 3
// baseline (speedup 1.0000x reference)
#include <cuda_runtime.h>
#include <cstdint>

#define DD 1024
#define HH 1024
#define NB 8
#define NS 40
#define NL 20
#define MI 320        // B*N rows of f
#define MJ 160        // B*L rows of v
#define MG 51200      // MI*MJ grounding pairs
#define NPAIR 780     // triu_indices(40, k=1)
#define MT 6240       // B*NPAIR text rows
#define K3 3072

// Scratch (static device globals; no runtime allocation anywhere)
__device__ float g_Apre[MI * HH];            // f @ Wf
__device__ float g_Cpre[MJ * HH];            // v @ Ws
__device__ float g_H1[(size_t)MG * HH];      // grounding hidden (210 MB)
__device__ float g_Xt[(size_t)MT * K3];      // text concat input (77 MB)
__device__ float g_Ht[(size_t)MT * HH];      // text hidden (26 MB)

// ---------------------------------------------------------------------------
// Generic SGEMM: C = act(A[MxK] @ B[KxN] + bias), row-major, N multiple of 64,
// K multiple of 16. 64x64 block tile, 256 threads, 4x4 per thread.
// Output / optional input selected device-side from the scratch globals so the
// host never needs cudaGetSymbolAddress.
//   a_sel: 0 -> use Aext, 1 -> g_Xt
//   c_sel: 0 -> g_Apre, 1 -> g_Cpre, 2 -> g_Ht
// ---------------------------------------------------------------------------
__global__ __launch_bounds__(256) void sgemm_kernel(
    const float* __restrict__ Aext, int a_sel, const float* __restrict__ Bm,
    const float* __restrict__ bias, int c_sel,
    int M, int N, int K, int do_relu)
{
    const float* A = (a_sel == 0) ? Aext : g_Xt;
    float* C = (c_sel == 0) ? g_Apre : (c_sel == 1) ? g_Cpre : g_Ht;

    __shared__ __align__(16) float As[16][66];
    __shared__ __align__(16) float Bs[16][64];
    int tid = threadIdx.x;
    int tx = tid & 15, ty = tid >> 4;
    int row0 = blockIdx.y * 64, col0 = blockIdx.x * 64;
    float acc[4][4] = {};
    for (int kt = 0; kt < K; kt += 16) {
        #pragma unroll
        for (int l = 0; l < 4; l++) {
            int idx = tid + l * 256;
            int m = idx >> 4, kk = idx & 15;
            int gr = row0 + m;
            As[kk][m] = (gr < M) ? A[(size_t)gr * K + kt + kk] : 0.f;
        }
        #pragma unroll
        for (int l = 0; l < 4; l++) {
            int idx = tid + l * 256;
            int kk = idx >> 6, c = idx & 63;
            Bs[kk][c] = Bm[(size_t)(kt + kk) * N + col0 + c];
        }
        __syncthreads();
        #pragma unroll
        for (int kk = 0; kk < 16; kk++) {
            float av[4], bv[4];
            #pragma unroll
            for (int i = 0; i < 4; i++) av[i] = As[kk][ty * 4 + i];
            float4 b4 = *(const float4*)&Bs[kk][tx * 4];
            bv[0] = b4.x; bv[1] = b4.y; bv[2] = b4.z; bv[3] = b4.w;
            #pragma unroll
            for (int i = 0; i < 4; i++)
                #pragma unroll
                for (int j = 0; j < 4; j++)
                    acc[i][j] += av[i] * bv[j];
        }
        __syncthreads();
    }
    #pragma unroll
    for (int i = 0; i < 4; i++) {
        int r = row0 + ty * 4 + i;
        if (r >= M) continue;
        #pragma unroll
        for (int j = 0; j < 4; j++) {
            int c = col0 + tx * 4 + j;
            float vl = acc[i][j];
            if (bias) vl += bias[c];
            if (do_relu) vl = fmaxf(vl, 0.f);
            C[(size_t)r * N + c] = vl;
        }
    }
}

// ---------------------------------------------------------------------------
// Grounding layer 1: H1[r,c] = relu((f_i ⊙ v_j) @ Wp + Apre[i,c] + Cpre[j,c] + b1[c])
// r = i*160 + j; M = 51200, N = K = 1024. A-tile generated on the fly.
// ---------------------------------------------------------------------------
__global__ __launch_bounds__(256) void ground_h1_kernel(
    const float* __restrict__ f, const float* __restrict__ v,
    const float* __restrict__ Wp, const float* __restrict__ b1)
{
    __shared__ __align__(16) float As[16][66];
    __shared__ __align__(16) float Bs[16][64];
    int tid = threadIdx.x;
    int tx = tid & 15, ty = tid >> 4;
    int row0 = blockIdx.y * 64, col0 = blockIdx.x * 64;
    float acc[4][4] = {};
    for (int kt = 0; kt < DD; kt += 16) {
        #pragma unroll
        for (int l = 0; l < 4; l++) {
            int idx = tid + l * 256;
            int m = idx >> 4, kk = idx & 15;
            int gr = row0 + m;
            int gi = gr / MJ, gj = gr - gi * MJ;
            As[kk][m] = f[(size_t)gi * DD + kt + kk] * v[(size_t)gj * DD + kt + kk];
        }
        #pragma unroll
        for (int l = 0; l < 4; l++) {
            int idx = tid + l * 256;
            int kk = idx >> 6, c = idx & 63;
            Bs[kk][c] = Wp[(size_t)(kt + kk) * HH + col0 + c];
        }
        __syncthreads();
        #pragma unroll
        for (int kk = 0; kk < 16; kk++) {
            float av[4], bv[4];
            #pragma unroll
            for (int i = 0; i < 4; i++) av[i] = As[kk][ty * 4 + i];
            float4 b4 = *(const float4*)&Bs[kk][tx * 4];
            bv[0] = b4.x; bv[1] = b4.y; bv[2] = b4.z; bv[3] = b4.w;
            #pragma unroll
            for (int i = 0; i < 4; i++)
                #pragma unroll
                for (int j = 0; j < 4; j++)
                    acc[i][j] += av[i] * bv[j];
        }
        __syncthreads();
    }
    #pragma unroll
    for (int i = 0; i < 4; i++) {
        int r = row0 + ty * 4 + i;
        int gi = r / MJ, gj = r - gi * MJ;
        #pragma unroll
        for (int j = 0; j < 4; j++) {
            int c = col0 + tx * 4 + j;
            float vl = acc[i][j] + g_Apre[(size_t)gi * HH + c] + g_Cpre[(size_t)gj * HH + c] + b1[c];
            g_H1[(size_t)r * HH + c] = fmaxf(vl, 0.f);
        }
    }
}

// ---------------------------------------------------------------------------
// Fused tail: out[r] = relu(H[r,:] @ W2 + b2) @ W3 + b3  (optionally * mask)
// h_sel: 0 -> g_H1, 1 -> g_Ht. Deterministic block reduction, no atomics.
// ---------------------------------------------------------------------------
__global__ __launch_bounds__(256) void tail_fused_kernel(
    int h_sel, const float* __restrict__ W2,
    const float* __restrict__ b2, const float* __restrict__ W3,
    const float* __restrict__ b3v, const float* __restrict__ sm,
    const float* __restrict__ im, float* __restrict__ outp,
    int M, int masked)
{
    const float* Hm = (h_sel == 0) ? g_H1 : g_Ht;
    __shared__ __align__(16) float As[16][66];
    __shared__ __align__(16) float Bs[16][64];
    __shared__ float red[64 * 16];
    int tid = threadIdx.x;
    int tx = tid & 15, ty = tid >> 4;
    int row0 = blockIdx.x * 64;
    float rsum[4] = {0.f, 0.f, 0.f, 0.f};
    for (int nc = 0; nc < HH; nc += 64) {
        float acc[4][4] = {};
        for (int kt = 0; kt < HH; kt += 16) {
            #pragma unroll
            for (int l = 0; l < 4; l++) {
                int idx = tid + l * 256;
                int m = idx >> 4, kk = idx & 15;
                int gr = row0 + m;
                As[kk][m] = (gr < M) ? Hm[(size_t)gr * HH + kt + kk] : 0.f;
            }
            #pragma unroll
            for (int l = 0; l < 4; l++) {
                int idx = tid + l * 256;
                int kk = idx >> 6, c = idx & 63;
                Bs[kk][c] = W2[(size_t)(kt + kk) * HH + nc + c];
            }
            __syncthreads();
            #pragma unroll
            for (int kk = 0; kk < 16; kk++) {
                float av[4], bv[4];
                #pragma unroll
                for (int i = 0; i < 4; i++) av[i] = As[kk][ty * 4 + i];
                float4 b4 = *(const float4*)&Bs[kk][tx * 4];
                bv[0] = b4.x; bv[1] = b4.y; bv[2] = b4.z; bv[3] = b4.w;
                #pragma unroll
                for (int i = 0; i < 4; i++)
                    #pragma unroll
                    for (int j = 0; j < 4; j++)
                        acc[i][j] += av[i] * bv[j];
            }
            __syncthreads();
        }
        #pragma unroll
        for (int j = 0; j < 4; j++) {
            int c = nc + tx * 4 + j;
            float w3 = W3[c], bb = b2[c];
            #pragma unroll
            for (int i = 0; i < 4; i++)
                rsum[i] += fmaxf(acc[i][j] + bb, 0.f) * w3;
        }
    }
    #pragma unroll
    for (int i = 0; i < 4; i++) red[(ty * 4 + i) * 16 + tx] = rsum[i];
    __syncthreads();
    if (tid < 64) {
        int r = row0 + tid;
        if (r < M) {
            float s = 0.f;
            #pragma unroll
            for (int t = 0; t < 16; t++) s += red[tid * 16 + t];
            s += b3v[0];
            if (masked) {
                int gi = r / MJ, gj = r - gi * MJ;
                s *= sm[gi] * im[gj];
            }
            outp[r] = s;
        }
    }
}

// ---------------------------------------------------------------------------
// Build text concat input: Xt[b*780+p] = [span[b,fi], span[b,si], span[b,fi]*span[b,si]]
// ---------------------------------------------------------------------------
__global__ void build_xt_kernel(const float* __restrict__ span)
{
    int r = blockIdx.x;
    int b = r / NPAIR, p = r - b * NPAIR;
    int n = 0, rem = p;
    while (rem >= (NS - 1 - n)) { rem -= (NS - 1 - n); n++; }
    int fi = n, si = n + 1 + rem;
    const float* a = span + ((size_t)b * NS + fi) * DD;
    const float* c = span + ((size_t)b * NS + si) * DD;
    float* x = g_Xt + (size_t)r * K3;
    for (int d = threadIdx.x; d < DD; d += blockDim.x) {
        float av = a[d], cv = c[d];
        x[d] = av;
        x[DD + d] = cv;
        x[2 * DD + d] = av * cv;
    }
}

// ---------------------------------------------------------------------------
// S[8][8] = chunk sums of 800 grounding scores; loss = bidirectional NCE.
// ---------------------------------------------------------------------------
__global__ void loss_kernel(const float* __restrict__ gsc, float* __restrict__ out0)
{
    __shared__ float S[64];
    __shared__ float red[256];
    int tid = threadIdx.x;
    int e = tid >> 2, q = tid & 3;
    float s = 0.f;
    const float* base = gsc + e * 800;
    for (int k = q; k < 800; k += 4) s += base[k];
    red[tid] = s;
    __syncthreads();
    if (q == 0) S[e] = red[tid] + red[tid + 1] + red[tid + 2] + red[tid + 3];
    __syncthreads();
    if (tid == 0) {
        float loss = 0.f;
        for (int a = 0; a < 8; a++) {
            float mx = -1e30f;
            for (int b = 0; b < 8; b++) mx = fmaxf(mx, S[a * 8 + b]);
            float se = 0.f;
            for (int b = 0; b < 8; b++) se += expf(S[a * 8 + b] - mx);
            float lse = mx + logf(se);
            for (int b = 0; b < 8; b++) loss -= (S[a * 8 + b] - lse);
        }
        for (int b = 0; b < 8; b++) {
            float mx = -1e30f;
            for (int a = 0; a < 8; a++) mx = fmaxf(mx, S[a * 8 + b]);
            float se = 0.f;
            for (int a = 0; a < 8; a++) se += expf(S[a * 8 + b] - mx);
            float lse = mx + logf(se);
            for (int a = 0; a < 8; a++) loss -= (S[a * 8 + b] - lse);
        }
        out0[0] = loss / 8.0f;
    }
}

extern "C" void kernel_launch(void* const* d_in, const int* in_sizes, int n_in,
                              void* d_out, int out_size)
{
    const float* span  = (const float*)d_in[0];
    const float* img   = (const float*)d_in[1];
    const float* smask = (const float*)d_in[2];
    const float* imask = (const float*)d_in[3];
    const float* tW1 = (const float*)d_in[4];
    const float* tb1 = (const float*)d_in[5];
    const float* tW2 = (const float*)d_in[6];
    const float* tb2 = (const float*)d_in[7];
    const float* tW3 = (const float*)d_in[8];
    const float* tb3 = (const float*)d_in[9];
    const float* gW1 = (const float*)d_in[10];
    const float* gb1 = (const float*)d_in[11];
    const float* gW2 = (const float*)d_in[12];
    const float* gb2 = (const float*)d_in[13];
    const float* gW3 = (const float*)d_in[14];
    const float* gb3 = (const float*)d_in[15];
    float* out = (float*)d_out;

    dim3 blk(256);

    // Grounding path
    sgemm_kernel<<<dim3(16, 5), blk>>>(span, 0, gW1, nullptr, 0, MI, HH, DD, 0);
    sgemm_kernel<<<dim3(16, 3), blk>>>(img, 0, gW1 + (size_t)DD * HH, nullptr, 1, MJ, HH, DD, 0);
    ground_h1_kernel<<<dim3(16, MG / 64), blk>>>(span, img, gW1 + (size_t)2 * DD * HH, gb1);
    tail_fused_kernel<<<dim3(MG / 64), blk>>>(0, gW2, gb2, gW3, gb3,
                                              smask, imask, out + 1, MG, 1);

    // Text path
    build_xt_kernel<<<dim3(MT), blk>>>(span);
    sgemm_kernel<<<dim3(16, (MT + 63) / 64), blk>>>(nullptr, 1, tW1, tb1, 2, MT, HH, K3, 1);
    tail_fused_kernel<<<dim3((MT + 63) / 64), blk>>>(1, tW2, tb2, tW3, tb3,
                                                     nullptr, nullptr, out + 1 + MG, MT, 0);

    // S and loss (reads masked grounding scores from out)
    loss_kernel<<<1, 256>>>(out + 1, out);
}

// round 5
// speedup vs baseline: 1.2433x; 1.2433x over previous
#include <cuda_runtime.h>
#include <cstdint>

#define DD 1024
#define HH 1024
#define NB 8
#define NS 40
#define NL 20
#define MI 320        // B*N rows of f
#define MJ 160        // B*L rows of v
#define MG 51200      // MI*MJ grounding pairs
#define NPAIR 780     // triu_indices(40, k=1)
#define MT 6240       // B*NPAIR text rows
#define K3 3072

#define BM 128
#define BN 128
#define BK 16

// Scratch (static device globals; no runtime allocation anywhere)
__device__ float g_Apre[MI * HH];            // f @ Wf
__device__ float g_Cpre[MJ * HH];            // v @ Ws
__device__ float g_H1[(size_t)MG * HH];      // grounding hidden (210 MB)
__device__ float g_Xt[(size_t)MT * K3];      // text concat input (77 MB)
__device__ float g_Ht[(size_t)MT * HH];      // text hidden (26 MB)

// ---------------------------------------------------------------------------
// Shared inner helpers for the 128x128x16 tile core (256 thr, 8x8/thread)
// ---------------------------------------------------------------------------
__device__ __forceinline__ void stage_store(
    float As[BK][BM + 4], float Bs[BK][BN],
    int tid, const float4* rA, const float4* rB)
{
    #pragma unroll
    for (int l = 0; l < 2; l++) {
        int idx = tid + l * 256;
        int row = idx >> 2, kq = idx & 3;
        As[kq * 4 + 0][row] = rA[l].x;
        As[kq * 4 + 1][row] = rA[l].y;
        As[kq * 4 + 2][row] = rA[l].z;
        As[kq * 4 + 3][row] = rA[l].w;
        int kk = idx >> 5, nq = idx & 31;
        *(float4*)&Bs[kk][nq * 4] = rB[l];
    }
}

__device__ __forceinline__ void mma_tile(
    const float As[BK][BM + 4], const float Bs[BK][BN],
    int tx, int ty, float acc[8][8])
{
    #pragma unroll
    for (int kk = 0; kk < BK; kk++) {
        float4 a0 = *(const float4*)&As[kk][ty * 8];
        float4 a1 = *(const float4*)&As[kk][ty * 8 + 4];
        float4 b0 = *(const float4*)&Bs[kk][tx * 8];
        float4 b1 = *(const float4*)&Bs[kk][tx * 8 + 4];
        float a8[8] = {a0.x, a0.y, a0.z, a0.w, a1.x, a1.y, a1.z, a1.w};
        float b8[8] = {b0.x, b0.y, b0.z, b0.w, b1.x, b1.y, b1.z, b1.w};
        #pragma unroll
        for (int i = 0; i < 8; i++)
            #pragma unroll
            for (int j = 0; j < 8; j++)
                acc[i][j] += a8[i] * b8[j];
    }
}

// ---------------------------------------------------------------------------
// Grounding layer 1 (fused A-gen):
// H1[r,c] = relu((f_i⊙v_j)@Wp + Apre[i,c] + Cpre[j,c] + b1[c]), r = i*160+j.
// M = 51200 (mult of 128), N = K = 1024.
// ---------------------------------------------------------------------------
__global__ __launch_bounds__(256, 2) void ground_h1_128(
    const float* __restrict__ f, const float* __restrict__ v,
    const float* __restrict__ Wp, const float* __restrict__ b1)
{
    __shared__ __align__(16) float As[BK][BM + 4];
    __shared__ __align__(16) float Bs[BK][BN];
    int tid = threadIdx.x;
    int tx = tid & 15, ty = tid >> 4;
    int row0 = blockIdx.y * BM, col0 = blockIdx.x * BN;
    float acc[8][8] = {};
    float4 rA[2], rB[2];

    // prologue loads (kt = 0)
    #pragma unroll
    for (int l = 0; l < 2; l++) {
        int idx = tid + l * 256;
        int row = idx >> 2, kq = idx & 3;
        int gr = row0 + row;
        int gi = gr / MJ, gj = gr - gi * MJ;
        float4 f4 = *(const float4*)&f[(size_t)gi * DD + kq * 4];
        float4 v4 = *(const float4*)&v[(size_t)gj * DD + kq * 4];
        rA[l] = make_float4(f4.x * v4.x, f4.y * v4.y, f4.z * v4.z, f4.w * v4.w);
        int kk = idx >> 5, nq = idx & 31;
        rB[l] = *(const float4*)&Wp[(size_t)kk * HH + col0 + nq * 4];
    }

    for (int kt = 0; kt < DD; kt += BK) {
        stage_store(As, Bs, tid, rA, rB);
        __syncthreads();
        if (kt + BK < DD) {
            int ktn = kt + BK;
            #pragma unroll
            for (int l = 0; l < 2; l++) {
                int idx = tid + l * 256;
                int row = idx >> 2, kq = idx & 3;
                int gr = row0 + row;
                int gi = gr / MJ, gj = gr - gi * MJ;
                float4 f4 = *(const float4*)&f[(size_t)gi * DD + ktn + kq * 4];
                float4 v4 = *(const float4*)&v[(size_t)gj * DD + ktn + kq * 4];
                rA[l] = make_float4(f4.x * v4.x, f4.y * v4.y, f4.z * v4.z, f4.w * v4.w);
                int kk = idx >> 5, nq = idx & 31;
                rB[l] = *(const float4*)&Wp[(size_t)(ktn + kk) * HH + col0 + nq * 4];
            }
        }
        mma_tile(As, Bs, tx, ty, acc);
        __syncthreads();
    }

    #pragma unroll
    for (int i = 0; i < 8; i++) {
        int r = row0 + ty * 8 + i;
        int gi = r / MJ, gj = r - gi * MJ;
        const float* ap = &g_Apre[(size_t)gi * HH + col0];
        const float* cp = &g_Cpre[(size_t)gj * HH + col0];
        float* hp = &g_H1[(size_t)r * HH + col0];
        #pragma unroll
        for (int j = 0; j < 8; j++) {
            int c = tx * 8 + j;
            float vl = acc[i][j] + ap[c] + cp[c] + b1[col0 + c];
            hp[c] = fmaxf(vl, 0.f);
        }
    }
}

// ---------------------------------------------------------------------------
// Text layer 1: g_Ht = relu(g_Xt @ tW1 + tb1). M = 6240, K = 3072, N = 1024.
// ---------------------------------------------------------------------------
__global__ __launch_bounds__(256, 2) void gemm_text1(
    const float* __restrict__ W1, const float* __restrict__ b1)
{
    __shared__ __align__(16) float As[BK][BM + 4];
    __shared__ __align__(16) float Bs[BK][BN];
    int tid = threadIdx.x;
    int tx = tid & 15, ty = tid >> 4;
    int row0 = blockIdx.y * BM, col0 = blockIdx.x * BN;
    float acc[8][8] = {};
    float4 rA[2], rB[2];
    const float4 zero4 = make_float4(0.f, 0.f, 0.f, 0.f);

    #pragma unroll
    for (int l = 0; l < 2; l++) {
        int idx = tid + l * 256;
        int row = idx >> 2, kq = idx & 3;
        int gr = row0 + row;
        rA[l] = (gr < MT) ? *(const float4*)&g_Xt[(size_t)gr * K3 + kq * 4] : zero4;
        int kk = idx >> 5, nq = idx & 31;
        rB[l] = *(const float4*)&W1[(size_t)kk * HH + col0 + nq * 4];
    }

    for (int kt = 0; kt < K3; kt += BK) {
        stage_store(As, Bs, tid, rA, rB);
        __syncthreads();
        if (kt + BK < K3) {
            int ktn = kt + BK;
            #pragma unroll
            for (int l = 0; l < 2; l++) {
                int idx = tid + l * 256;
                int row = idx >> 2, kq = idx & 3;
                int gr = row0 + row;
                rA[l] = (gr < MT) ? *(const float4*)&g_Xt[(size_t)gr * K3 + ktn + kq * 4] : zero4;
                int kk = idx >> 5, nq = idx & 31;
                rB[l] = *(const float4*)&W1[(size_t)(ktn + kk) * HH + col0 + nq * 4];
            }
        }
        mma_tile(As, Bs, tx, ty, acc);
        __syncthreads();
    }

    #pragma unroll
    for (int i = 0; i < 8; i++) {
        int r = row0 + ty * 8 + i;
        if (r >= MT) continue;
        float* hp = &g_Ht[(size_t)r * HH + col0];
        #pragma unroll
        for (int j = 0; j < 8; j++) {
            int c = tx * 8 + j;
            hp[c] = fmaxf(acc[i][j] + b1[col0 + c], 0.f);
        }
    }
}

// ---------------------------------------------------------------------------
// Fused tail: out[r] = relu(H[r,:] @ W2 + b2) @ W3 + b3 (optionally * mask).
// 128-row block, loops over 128-col chunks of W2. Deterministic reduction.
// h_sel: 0 -> g_H1, 1 -> g_Ht.
// ---------------------------------------------------------------------------
__global__ __launch_bounds__(256, 2) void tail128(
    int h_sel, const float* __restrict__ W2,
    const float* __restrict__ b2, const float* __restrict__ W3,
    const float* __restrict__ b3v, const float* __restrict__ sm,
    const float* __restrict__ im, float* __restrict__ outp,
    int M, int masked)
{
    const float* Hm = (h_sel == 0) ? g_H1 : g_Ht;
    __shared__ __align__(16) float As[BK][BM + 4];
    __shared__ __align__(16) float Bs[BK][BN];
    __shared__ float red[BM * 16];
    int tid = threadIdx.x;
    int tx = tid & 15, ty = tid >> 4;
    int row0 = blockIdx.x * BM;
    float rsum[8] = {};
    const float4 zero4 = make_float4(0.f, 0.f, 0.f, 0.f);

    for (int nc = 0; nc < HH; nc += BN) {
        float acc[8][8] = {};
        float4 rA[2], rB[2];
        #pragma unroll
        for (int l = 0; l < 2; l++) {
            int idx = tid + l * 256;
            int row = idx >> 2, kq = idx & 3;
            int gr = row0 + row;
            rA[l] = (gr < M) ? *(const float4*)&Hm[(size_t)gr * HH + kq * 4] : zero4;
            int kk = idx >> 5, nq = idx & 31;
            rB[l] = *(const float4*)&W2[(size_t)kk * HH + nc + nq * 4];
        }
        for (int kt = 0; kt < HH; kt += BK) {
            stage_store(As, Bs, tid, rA, rB);
            __syncthreads();
            if (kt + BK < HH) {
                int ktn = kt + BK;
                #pragma unroll
                for (int l = 0; l < 2; l++) {
                    int idx = tid + l * 256;
                    int row = idx >> 2, kq = idx & 3;
                    int gr = row0 + row;
                    rA[l] = (gr < M) ? *(const float4*)&Hm[(size_t)gr * HH + ktn + kq * 4] : zero4;
                    int kk = idx >> 5, nq = idx & 31;
                    rB[l] = *(const float4*)&W2[(size_t)(ktn + kk) * HH + nc + nq * 4];
                }
            }
            mma_tile(As, Bs, tx, ty, acc);
            __syncthreads();
        }
        #pragma unroll
        for (int j = 0; j < 8; j++) {
            int c = nc + tx * 8 + j;
            float w3 = W3[c], bb = b2[c];
            #pragma unroll
            for (int i = 0; i < 8; i++)
                rsum[i] += fmaxf(acc[i][j] + bb, 0.f) * w3;
        }
    }

    #pragma unroll
    for (int i = 0; i < 8; i++) red[(ty * 8 + i) * 16 + tx] = rsum[i];
    __syncthreads();
    if (tid < BM) {
        int r = row0 + tid;
        if (r < M) {
            float s = 0.f;
            #pragma unroll
            for (int t = 0; t < 16; t++) s += red[tid * 16 + t];
            s += b3v[0];
            if (masked) {
                int gi = r / MJ, gj = r - gi * MJ;
                s *= sm[gi] * im[gj];
            }
            outp[r] = s;
        }
    }
}

// ---------------------------------------------------------------------------
// Small SGEMM (64x64 tile) for the two tiny pre-GEMMs f@Wf, v@Ws.
// c_sel: 0 -> g_Apre, 1 -> g_Cpre.
// ---------------------------------------------------------------------------
__global__ __launch_bounds__(256) void sgemm_small(
    const float* __restrict__ A, const float* __restrict__ Bm,
    int c_sel, int M, int N, int K)
{
    float* C = (c_sel == 0) ? g_Apre : g_Cpre;
    __shared__ __align__(16) float As[16][66];
    __shared__ __align__(16) float Bs[16][64];
    int tid = threadIdx.x;
    int tx = tid & 15, ty = tid >> 4;
    int row0 = blockIdx.y * 64, col0 = blockIdx.x * 64;
    float acc[4][4] = {};
    for (int kt = 0; kt < K; kt += 16) {
        #pragma unroll
        for (int l = 0; l < 4; l++) {
            int idx = tid + l * 256;
            int m = idx >> 4, kk = idx & 15;
            int gr = row0 + m;
            As[kk][m] = (gr < M) ? A[(size_t)gr * K + kt + kk] : 0.f;
        }
        #pragma unroll
        for (int l = 0; l < 4; l++) {
            int idx = tid + l * 256;
            int kk = idx >> 6, c = idx & 63;
            Bs[kk][c] = Bm[(size_t)(kt + kk) * N + col0 + c];
        }
        __syncthreads();
        #pragma unroll
        for (int kk = 0; kk < 16; kk++) {
            float av[4];
            #pragma unroll
            for (int i = 0; i < 4; i++) av[i] = As[kk][ty * 4 + i];
            float4 b4 = *(const float4*)&Bs[kk][tx * 4];
            float bv[4] = {b4.x, b4.y, b4.z, b4.w};
            #pragma unroll
            for (int i = 0; i < 4; i++)
                #pragma unroll
                for (int j = 0; j < 4; j++)
                    acc[i][j] += av[i] * bv[j];
        }
        __syncthreads();
    }
    #pragma unroll
    for (int i = 0; i < 4; i++) {
        int r = row0 + ty * 4 + i;
        if (r >= M) continue;
        #pragma unroll
        for (int j = 0; j < 4; j++)
            C[(size_t)r * N + col0 + tx * 4 + j] = acc[i][j];
    }
}

// ---------------------------------------------------------------------------
// Build text concat input: Xt[b*780+p] = [span[fi], span[si], span[fi]*span[si]]
// ---------------------------------------------------------------------------
__global__ void build_xt_kernel(const float* __restrict__ span)
{
    int r = blockIdx.x;
    int b = r / NPAIR, p = r - b * NPAIR;
    int n = 0, rem = p;
    while (rem >= (NS - 1 - n)) { rem -= (NS - 1 - n); n++; }
    int fi = n, si = n + 1 + rem;
    const float* a = span + ((size_t)b * NS + fi) * DD;
    const float* c = span + ((size_t)b * NS + si) * DD;
    float* x = g_Xt + (size_t)r * K3;
    for (int d = threadIdx.x; d < DD; d += blockDim.x) {
        float av = a[d], cv = c[d];
        x[d] = av;
        x[DD + d] = cv;
        x[2 * DD + d] = av * cv;
    }
}

// ---------------------------------------------------------------------------
// S[8][8] = chunk sums of 800 grounding scores; loss = bidirectional NCE.
// ---------------------------------------------------------------------------
__global__ void loss_kernel(const float* __restrict__ gsc, float* __restrict__ out0)
{
    __shared__ float S[64];
    __shared__ float red[256];
    int tid = threadIdx.x;
    int e = tid >> 2, q = tid & 3;
    float s = 0.f;
    const float* base = gsc + e * 800;
    for (int k = q; k < 800; k += 4) s += base[k];
    red[tid] = s;
    __syncthreads();
    if (q == 0) S[e] = red[tid] + red[tid + 1] + red[tid + 2] + red[tid + 3];
    __syncthreads();
    if (tid == 0) {
        float loss = 0.f;
        for (int a = 0; a < 8; a++) {
            float mx = -1e30f;
            for (int b = 0; b < 8; b++) mx = fmaxf(mx, S[a * 8 + b]);
            float se = 0.f;
            for (int b = 0; b < 8; b++) se += expf(S[a * 8 + b] - mx);
            float lse = mx + logf(se);
            for (int b = 0; b < 8; b++) loss -= (S[a * 8 + b] - lse);
        }
        for (int b = 0; b < 8; b++) {
            float mx = -1e30f;
            for (int a = 0; a < 8; a++) mx = fmaxf(mx, S[a * 8 + b]);
            float se = 0.f;
            for (int a = 0; a < 8; a++) se += expf(S[a * 8 + b] - mx);
            float lse = mx + logf(se);
            for (int a = 0; a < 8; a++) loss -= (S[a * 8 + b] - lse);
        }
        out0[0] = loss / 8.0f;
    }
}

extern "C" void kernel_launch(void* const* d_in, const int* in_sizes, int n_in,
                              void* d_out, int out_size)
{
    const float* span  = (const float*)d_in[0];
    const float* img   = (const float*)d_in[1];
    const float* smask = (const float*)d_in[2];
    const float* imask = (const float*)d_in[3];
    const float* tW1 = (const float*)d_in[4];
    const float* tb1 = (const float*)d_in[5];
    const float* tW2 = (const float*)d_in[6];
    const float* tb2 = (const float*)d_in[7];
    const float* tW3 = (const float*)d_in[8];
    const float* tb3 = (const float*)d_in[9];
    const float* gW1 = (const float*)d_in[10];
    const float* gb1 = (const float*)d_in[11];
    const float* gW2 = (const float*)d_in[12];
    const float* gb2 = (const float*)d_in[13];
    const float* gW3 = (const float*)d_in[14];
    const float* gb3 = (const float*)d_in[15];
    float* out = (float*)d_out;

    dim3 blk(256);

    // Grounding path
    sgemm_small<<<dim3(16, 5), blk>>>(span, gW1, 0, MI, HH, DD);
    sgemm_small<<<dim3(16, 3), blk>>>(img, gW1 + (size_t)DD * HH, 1, MJ, HH, DD);
    ground_h1_128<<<dim3(HH / BN, MG / BM), blk>>>(span, img, gW1 + (size_t)2 * DD * HH, gb1);
    tail128<<<dim3(MG / BM), blk>>>(0, gW2, gb2, gW3, gb3, smask, imask, out + 1, MG, 1);

    // Text path
    build_xt_kernel<<<dim3(MT), blk>>>(span);
    gemm_text1<<<dim3(HH / BN, (MT + BM - 1) / BM), blk>>>(tW1, tb1);
    tail128<<<dim3((MT + BM - 1) / BM), blk>>>(1, tW2, tb2, tW3, tb3,
                                               nullptr, nullptr, out + 1 + MG, MT, 0);

    // S and loss (reads masked grounding scores from out)
    loss_kernel<<<1, 256>>>(out + 1, out);
}

// round 7
// speedup vs baseline: 3.0042x; 2.4163x over previous
#include <cuda_runtime.h>
#include <cstdint>

#define DD 1024
#define HH 1024
#define NB 8
#define NS 40
#define NL 20
#define MI 320        // B*N rows of f
#define MJ 160        // B*L rows of v
#define MG 51200      // MI*MJ grounding pairs
#define NPAIR 780     // triu_indices(40, k=1)
#define MT 6240       // B*NPAIR text rows
#define K3 3072

#define BM 128
#define BN 128
#define BK 16
#define PAD 8

// Scratch (static device globals; no runtime allocation anywhere)
__device__ float g_Apre[MI * HH];            // f @ Wf
__device__ float g_Cpre[MJ * HH];            // v @ Ws
__device__ float g_H1[(size_t)MG * HH];      // grounding hidden (210 MB)
__device__ float g_Xt[(size_t)MT * K3];      // text concat input (77 MB)
__device__ float g_Ht[(size_t)MT * HH];      // text hidden (26 MB)

// ---------------------------------------------------------------------------
// TF32 helpers
// ---------------------------------------------------------------------------
__device__ __forceinline__ uint32_t f2tf(float x) {
    uint32_t r;
    asm("cvt.rna.tf32.f32 %0, %1;" : "=r"(r) : "f"(x));
    return r;
}

__device__ __forceinline__ void mma_tf32(float* c,
    uint32_t a0, uint32_t a1, uint32_t a2, uint32_t a3,
    uint32_t b0, uint32_t b1)
{
    asm volatile(
        "mma.sync.aligned.m16n8k8.row.col.f32.tf32.tf32.f32 "
        "{%0,%1,%2,%3}, {%4,%5,%6,%7}, {%8,%9}, {%0,%1,%2,%3};\n"
        : "+f"(c[0]), "+f"(c[1]), "+f"(c[2]), "+f"(c[3])
        : "r"(a0), "r"(a1), "r"(a2), "r"(a3), "r"(b0), "r"(b1));
}

// Stage fp32 registers -> tf32 smem tiles. A transposed to [k][m], B as [k][n].
__device__ __forceinline__ void stage_tiles(
    uint32_t As[BK][BM + PAD], uint32_t Bs[BK][BN + PAD],
    int tid, const float4* rA, const float4* rB)
{
    #pragma unroll
    for (int l = 0; l < 2; l++) {
        int idx = tid + l * 256;
        int row = idx >> 2, kq = idx & 3;
        As[kq * 4 + 0][row] = f2tf(rA[l].x);
        As[kq * 4 + 1][row] = f2tf(rA[l].y);
        As[kq * 4 + 2][row] = f2tf(rA[l].z);
        As[kq * 4 + 3][row] = f2tf(rA[l].w);
        int kk = idx >> 5, nq = idx & 31;
        uint4 bb = make_uint4(f2tf(rB[l].x), f2tf(rB[l].y), f2tf(rB[l].z), f2tf(rB[l].w));
        *(uint4*)&Bs[kk][nq * 4] = bb;
    }
}

// One BK=16 stage of MMAs: warp tile 64x32 = 4 m-tiles x 4 n-tiles.
__device__ __forceinline__ void mma_stage(
    const uint32_t As[BK][BM + PAD], const uint32_t Bs[BK][BN + PAD],
    int wrow, int wcol, int fr, int fc, float acc[4][4][4])
{
    #pragma unroll
    for (int ks = 0; ks < BK; ks += 8) {
        uint32_t af[4][4], bf[4][2];
        #pragma unroll
        for (int mt = 0; mt < 4; mt++) {
            int m = wrow + mt * 16 + fr;
            af[mt][0] = As[ks + fc][m];
            af[mt][1] = As[ks + fc][m + 8];
            af[mt][2] = As[ks + fc + 4][m];
            af[mt][3] = As[ks + fc + 4][m + 8];
        }
        #pragma unroll
        for (int nt = 0; nt < 4; nt++) {
            int n = wcol + nt * 8 + fr;
            bf[nt][0] = Bs[ks + fc][n];
            bf[nt][1] = Bs[ks + fc + 4][n];
        }
        #pragma unroll
        for (int mt = 0; mt < 4; mt++)
            #pragma unroll
            for (int nt = 0; nt < 4; nt++)
                mma_tf32(acc[mt][nt],
                         af[mt][0], af[mt][1], af[mt][2], af[mt][3],
                         bf[nt][0], bf[nt][1]);
    }
}

// ---------------------------------------------------------------------------
// Grounding layer 1 (fused A-gen, tf32 tensor cores):
// H1[r,c] = relu((f_i⊙v_j)@Wp + Apre[i,c] + Cpre[j,c] + b1[c]), r = i*160+j.
// ---------------------------------------------------------------------------
__global__ __launch_bounds__(256, 2) void ground_h1_tc(
    const float* __restrict__ f, const float* __restrict__ v,
    const float* __restrict__ Wp, const float* __restrict__ b1)
{
    __shared__ uint32_t As[BK][BM + PAD];
    __shared__ uint32_t Bs[BK][BN + PAD];
    int tid = threadIdx.x;
    int wid = tid >> 5, lane = tid & 31;
    int wm = wid & 1, wn = wid >> 1;
    int wrow = wm * 64, wcol = wn * 32;
    int fr = lane >> 2, fc = lane & 3;
    int row0 = blockIdx.y * BM, col0 = blockIdx.x * BN;
    float acc[4][4][4] = {};
    float4 rA[2], rB[2];

    #pragma unroll
    for (int l = 0; l < 2; l++) {
        int idx = tid + l * 256;
        int row = idx >> 2, kq = idx & 3;
        int gr = row0 + row;
        int gi = gr / MJ, gj = gr - gi * MJ;
        float4 f4 = *(const float4*)&f[(size_t)gi * DD + kq * 4];
        float4 v4 = *(const float4*)&v[(size_t)gj * DD + kq * 4];
        rA[l] = make_float4(f4.x * v4.x, f4.y * v4.y, f4.z * v4.z, f4.w * v4.w);
        int kk = idx >> 5, nq = idx & 31;
        rB[l] = *(const float4*)&Wp[(size_t)kk * HH + col0 + nq * 4];
    }

    for (int kt = 0; kt < DD; kt += BK) {
        stage_tiles(As, Bs, tid, rA, rB);
        __syncthreads();
        if (kt + BK < DD) {
            int ktn = kt + BK;
            #pragma unroll
            for (int l = 0; l < 2; l++) {
                int idx = tid + l * 256;
                int row = idx >> 2, kq = idx & 3;
                int gr = row0 + row;
                int gi = gr / MJ, gj = gr - gi * MJ;
                float4 f4 = *(const float4*)&f[(size_t)gi * DD + ktn + kq * 4];
                float4 v4 = *(const float4*)&v[(size_t)gj * DD + ktn + kq * 4];
                rA[l] = make_float4(f4.x * v4.x, f4.y * v4.y, f4.z * v4.z, f4.w * v4.w);
                int kk = idx >> 5, nq = idx & 31;
                rB[l] = *(const float4*)&Wp[(size_t)(ktn + kk) * HH + col0 + nq * 4];
            }
        }
        mma_stage(As, Bs, wrow, wcol, fr, fc, acc);
        __syncthreads();
    }

    #pragma unroll
    for (int mt = 0; mt < 4; mt++) {
        #pragma unroll
        for (int h = 0; h < 2; h++) {
            int r = row0 + wrow + mt * 16 + fr + h * 8;
            int gi = r / MJ, gj = r - gi * MJ;
            const float* ap = &g_Apre[(size_t)gi * HH];
            const float* cp = &g_Cpre[(size_t)gj * HH];
            float* hp = &g_H1[(size_t)r * HH];
            #pragma unroll
            for (int nt = 0; nt < 4; nt++) {
                int c = col0 + wcol + nt * 8 + fc * 2;
                float x0 = acc[mt][nt][h * 2 + 0] + ap[c] + cp[c] + b1[c];
                float x1 = acc[mt][nt][h * 2 + 1] + ap[c + 1] + cp[c + 1] + b1[c + 1];
                *(float2*)&hp[c] = make_float2(fmaxf(x0, 0.f), fmaxf(x1, 0.f));
            }
        }
    }
}

// ---------------------------------------------------------------------------
// Text layer 1: g_Ht = relu(g_Xt @ tW1 + tb1). M = 6240, K = 3072, N = 1024.
// ---------------------------------------------------------------------------
__global__ __launch_bounds__(256, 2) void text1_tc(
    const float* __restrict__ W1, const float* __restrict__ b1)
{
    __shared__ uint32_t As[BK][BM + PAD];
    __shared__ uint32_t Bs[BK][BN + PAD];
    int tid = threadIdx.x;
    int wid = tid >> 5, lane = tid & 31;
    int wm = wid & 1, wn = wid >> 1;
    int wrow = wm * 64, wcol = wn * 32;
    int fr = lane >> 2, fc = lane & 3;
    int row0 = blockIdx.y * BM, col0 = blockIdx.x * BN;
    float acc[4][4][4] = {};
    float4 rA[2], rB[2];
    const float4 zero4 = make_float4(0.f, 0.f, 0.f, 0.f);

    #pragma unroll
    for (int l = 0; l < 2; l++) {
        int idx = tid + l * 256;
        int row = idx >> 2, kq = idx & 3;
        int gr = row0 + row;
        rA[l] = (gr < MT) ? *(const float4*)&g_Xt[(size_t)gr * K3 + kq * 4] : zero4;
        int kk = idx >> 5, nq = idx & 31;
        rB[l] = *(const float4*)&W1[(size_t)kk * HH + col0 + nq * 4];
    }

    for (int kt = 0; kt < K3; kt += BK) {
        stage_tiles(As, Bs, tid, rA, rB);
        __syncthreads();
        if (kt + BK < K3) {
            int ktn = kt + BK;
            #pragma unroll
            for (int l = 0; l < 2; l++) {
                int idx = tid + l * 256;
                int row = idx >> 2, kq = idx & 3;
                int gr = row0 + row;
                rA[l] = (gr < MT) ? *(const float4*)&g_Xt[(size_t)gr * K3 + ktn + kq * 4] : zero4;
                int kk = idx >> 5, nq = idx & 31;
                rB[l] = *(const float4*)&W1[(size_t)(ktn + kk) * HH + col0 + nq * 4];
            }
        }
        mma_stage(As, Bs, wrow, wcol, fr, fc, acc);
        __syncthreads();
    }

    #pragma unroll
    for (int mt = 0; mt < 4; mt++) {
        #pragma unroll
        for (int h = 0; h < 2; h++) {
            int r = row0 + wrow + mt * 16 + fr + h * 8;
            if (r >= MT) continue;
            float* hp = &g_Ht[(size_t)r * HH];
            #pragma unroll
            for (int nt = 0; nt < 4; nt++) {
                int c = col0 + wcol + nt * 8 + fc * 2;
                float x0 = acc[mt][nt][h * 2 + 0] + b1[c];
                float x1 = acc[mt][nt][h * 2 + 1] + b1[c + 1];
                *(float2*)&hp[c] = make_float2(fmaxf(x0, 0.f), fmaxf(x1, 0.f));
            }
        }
    }
}

// ---------------------------------------------------------------------------
// Fused tail (tf32): out[r] = relu(H[r,:]@W2 + b2) @ W3 + b3 (optional mask).
// h_sel: 0 -> g_H1, 1 -> g_Ht. Deterministic reduction.
// ---------------------------------------------------------------------------
__global__ __launch_bounds__(256, 2) void tail_tc(
    int h_sel, const float* __restrict__ W2,
    const float* __restrict__ b2, const float* __restrict__ W3,
    const float* __restrict__ b3v, const float* __restrict__ sm,
    const float* __restrict__ im, float* __restrict__ outp,
    int M, int masked)
{
    const float* Hm = (h_sel == 0) ? g_H1 : g_Ht;
    __shared__ uint32_t As[BK][BM + PAD];
    __shared__ uint32_t Bs[BK][BN + PAD];
    __shared__ float red[BM * 16];
    int tid = threadIdx.x;
    int wid = tid >> 5, lane = tid & 31;
    int wm = wid & 1, wn = wid >> 1;
    int wrow = wm * 64, wcol = wn * 32;
    int fr = lane >> 2, fc = lane & 3;
    int row0 = blockIdx.x * BM;
    float rsum[4][2] = {};
    const float4 zero4 = make_float4(0.f, 0.f, 0.f, 0.f);

    for (int nc = 0; nc < HH; nc += BN) {
        float acc[4][4][4] = {};
        float4 rA[2], rB[2];
        #pragma unroll
        for (int l = 0; l < 2; l++) {
            int idx = tid + l * 256;
            int row = idx >> 2, kq = idx & 3;
            int gr = row0 + row;
            rA[l] = (gr < M) ? *(const float4*)&Hm[(size_t)gr * HH + kq * 4] : zero4;
            int kk = idx >> 5, nq = idx & 31;
            rB[l] = *(const float4*)&W2[(size_t)kk * HH + nc + nq * 4];
        }
        for (int kt = 0; kt < HH; kt += BK) {
            stage_tiles(As, Bs, tid, rA, rB);
            __syncthreads();
            if (kt + BK < HH) {
                int ktn = kt + BK;
                #pragma unroll
                for (int l = 0; l < 2; l++) {
                    int idx = tid + l * 256;
                    int row = idx >> 2, kq = idx & 3;
                    int gr = row0 + row;
                    rA[l] = (gr < M) ? *(const float4*)&Hm[(size_t)gr * HH + ktn + kq * 4] : zero4;
                    int kk = idx >> 5, nq = idx & 31;
                    rB[l] = *(const float4*)&W2[(size_t)(ktn + kk) * HH + nc + nq * 4];
                }
            }
            mma_stage(As, Bs, wrow, wcol, fr, fc, acc);
            __syncthreads();
        }
        #pragma unroll
        for (int mt = 0; mt < 4; mt++) {
            #pragma unroll
            for (int nt = 0; nt < 4; nt++) {
                int c = nc + wcol + nt * 8 + fc * 2;
                float w30 = W3[c], w31 = W3[c + 1];
                float b20 = b2[c], b21 = b2[c + 1];
                rsum[mt][0] += fmaxf(acc[mt][nt][0] + b20, 0.f) * w30
                             + fmaxf(acc[mt][nt][1] + b21, 0.f) * w31;
                rsum[mt][1] += fmaxf(acc[mt][nt][2] + b20, 0.f) * w30
                             + fmaxf(acc[mt][nt][3] + b21, 0.f) * w31;
            }
        }
    }

    #pragma unroll
    for (int mt = 0; mt < 4; mt++)
        #pragma unroll
        for (int h = 0; h < 2; h++) {
            int row = wrow + mt * 16 + fr + h * 8;
            red[row * 16 + wn * 4 + fc] = rsum[mt][h];
        }
    __syncthreads();
    if (tid < BM) {
        int r = row0 + tid;
        if (r < M) {
            float s = 0.f;
            #pragma unroll
            for (int t = 0; t < 16; t++) s += red[tid * 16 + t];
            s += b3v[0];
            if (masked) {
                int gi = r / MJ, gj = r - gi * MJ;
                s *= sm[gi] * im[gj];
            }
            outp[r] = s;
        }
    }
}

// ---------------------------------------------------------------------------
// Small SGEMM (fp32, 64x64 tile) for the two tiny pre-GEMMs f@Wf, v@Ws.
// c_sel: 0 -> g_Apre, 1 -> g_Cpre.
// ---------------------------------------------------------------------------
__global__ __launch_bounds__(256) void sgemm_small(
    const float* __restrict__ A, const float* __restrict__ Bm,
    int c_sel, int M, int N, int K)
{
    float* C = (c_sel == 0) ? g_Apre : g_Cpre;
    __shared__ __align__(16) float As[16][66];
    __shared__ __align__(16) float Bs[16][64];
    int tid = threadIdx.x;
    int tx = tid & 15, ty = tid >> 4;
    int row0 = blockIdx.y * 64, col0 = blockIdx.x * 64;
    float acc[4][4] = {};
    for (int kt = 0; kt < K; kt += 16) {
        #pragma unroll
        for (int l = 0; l < 4; l++) {
            int idx = tid + l * 256;
            int m = idx >> 4, kk = idx & 15;
            int gr = row0 + m;
            As[kk][m] = (gr < M) ? A[(size_t)gr * K + kt + kk] : 0.f;
        }
        #pragma unroll
        for (int l = 0; l < 4; l++) {
            int idx = tid + l * 256;
            int kk = idx >> 6, c = idx & 63;
            Bs[kk][c] = Bm[(size_t)(kt + kk) * N + col0 + c];
        }
        __syncthreads();
        #pragma unroll
        for (int kk = 0; kk < 16; kk++) {
            float av[4];
            #pragma unroll
            for (int i = 0; i < 4; i++) av[i] = As[kk][ty * 4 + i];
            float4 b4 = *(const float4*)&Bs[kk][tx * 4];
            float bv[4] = {b4.x, b4.y, b4.z, b4.w};
            #pragma unroll
            for (int i = 0; i < 4; i++)
                #pragma unroll
                for (int j = 0; j < 4; j++)
                    acc[i][j] += av[i] * bv[j];
        }
        __syncthreads();
    }
    #pragma unroll
    for (int i = 0; i < 4; i++) {
        int r = row0 + ty * 4 + i;
        if (r >= M) continue;
        #pragma unroll
        for (int j = 0; j < 4; j++)
            C[(size_t)r * N + col0 + tx * 4 + j] = acc[i][j];
    }
}

// ---------------------------------------------------------------------------
// Build text concat input: Xt[b*780+p] = [span[fi], span[si], span[fi]*span[si]]
// ---------------------------------------------------------------------------
__global__ void build_xt_kernel(const float* __restrict__ span)
{
    int r = blockIdx.x;
    int b = r / NPAIR, p = r - b * NPAIR;
    int n = 0, rem = p;
    while (rem >= (NS - 1 - n)) { rem -= (NS - 1 - n); n++; }
    int fi = n, si = n + 1 + rem;
    const float* a = span + ((size_t)b * NS + fi) * DD;
    const float* c = span + ((size_t)b * NS + si) * DD;
    float* x = g_Xt + (size_t)r * K3;
    for (int d = threadIdx.x; d < DD; d += blockDim.x) {
        float av = a[d], cv = c[d];
        x[d] = av;
        x[DD + d] = cv;
        x[2 * DD + d] = av * cv;
    }
}

// ---------------------------------------------------------------------------
// S[8][8] = chunk sums of 800 grounding scores; loss = bidirectional NCE.
// ---------------------------------------------------------------------------
__global__ void loss_kernel(const float* __restrict__ gsc, float* __restrict__ out0)
{
    __shared__ float S[64];
    __shared__ float red[256];
    int tid = threadIdx.x;
    int e = tid >> 2, q = tid & 3;
    float s = 0.f;
    const float* base = gsc + e * 800;
    for (int k = q; k < 800; k += 4) s += base[k];
    red[tid] = s;
    __syncthreads();
    if (q == 0) S[e] = red[tid] + red[tid + 1] + red[tid + 2] + red[tid + 3];
    __syncthreads();
    if (tid == 0) {
        float loss = 0.f;
        for (int a = 0; a < 8; a++) {
            float mx = -1e30f;
            for (int b = 0; b < 8; b++) mx = fmaxf(mx, S[a * 8 + b]);
            float se = 0.f;
            for (int b = 0; b < 8; b++) se += expf(S[a * 8 + b] - mx);
            float lse = mx + logf(se);
            for (int b = 0; b < 8; b++) loss -= (S[a * 8 + b] - lse);
        }
        for (int b = 0; b < 8; b++) {
            float mx = -1e30f;
            for (int a = 0; a < 8; a++) mx = fmaxf(mx, S[a * 8 + b]);
            float se = 0.f;
            for (int a = 0; a < 8; a++) se += expf(S[a * 8 + b] - mx);
            float lse = mx + logf(se);
            for (int a = 0; a < 8; a++) loss -= (S[a * 8 + b] - lse);
        }
        out0[0] = loss / 8.0f;
    }
}

extern "C" void kernel_launch(void* const* d_in, const int* in_sizes, int n_in,
                              void* d_out, int out_size)
{
    const float* span  = (const float*)d_in[0];
    const float* img   = (const float*)d_in[1];
    const float* smask = (const float*)d_in[2];
    const float* imask = (const float*)d_in[3];
    const float* tW1 = (const float*)d_in[4];
    const float* tb1 = (const float*)d_in[5];
    const float* tW2 = (const float*)d_in[6];
    const float* tb2 = (const float*)d_in[7];
    const float* tW3 = (const float*)d_in[8];
    const float* tb3 = (const float*)d_in[9];
    const float* gW1 = (const float*)d_in[10];
    const float* gb1 = (const float*)d_in[11];
    const float* gW2 = (const float*)d_in[12];
    const float* gb2 = (const float*)d_in[13];
    const float* gW3 = (const float*)d_in[14];
    const float* gb3 = (const float*)d_in[15];
    float* out = (float*)d_out;

    dim3 blk(256);

    // Grounding path
    sgemm_small<<<dim3(16, 5), blk>>>(span, gW1, 0, MI, HH, DD);
    sgemm_small<<<dim3(16, 3), blk>>>(img, gW1 + (size_t)DD * HH, 1, MJ, HH, DD);
    ground_h1_tc<<<dim3(HH / BN, MG / BM), blk>>>(span, img, gW1 + (size_t)2 * DD * HH, gb1);
    tail_tc<<<dim3(MG / BM), blk>>>(0, gW2, gb2, gW3, gb3, smask, imask, out + 1, MG, 1);

    // Text path
    build_xt_kernel<<<dim3(MT), blk>>>(span);
    text1_tc<<<dim3(HH / BN, (MT + BM - 1) / BM), blk>>>(tW1, tb1);
    tail_tc<<<dim3((MT + BM - 1) / BM), blk>>>(1, tW2, tb2, tW3, tb3,
                                               nullptr, nullptr, out + 1 + MG, MT, 0);

    // S and loss (reads masked grounding scores from out)
    loss_kernel<<<1, 256>>>(out + 1, out);
}

// round 9
// speedup vs baseline: 3.0790x; 1.0249x over previous
#include <cuda_runtime.h>
#include <cstdint>

#define DD 1024
#define HH 1024
#define NB 8
#define NS 40
#define NL 20
#define MI 320        // B*N rows of f
#define MJ 160        // B*L rows of v
#define MG 51200      // MI*MJ grounding pairs
#define NPAIR 780     // triu_indices(40, k=1)
#define MT 6240       // B*NPAIR text rows
#define K3 3072

#define BM 128
#define BN 128
#define BK 16
#define ASTR 520      // plane stride in floats: BM*4 + 8 (conflict-free chunks)

// Scratch (static device globals; no runtime allocation anywhere)
__device__ float g_Apre[MI * HH];            // f @ Wf
__device__ float g_Cpre[MJ * HH];            // v @ Ws
__device__ float g_H1[(size_t)MG * HH];      // grounding hidden (210 MB)
__device__ float g_Xt[(size_t)MT * K3];      // text concat input (77 MB)
__device__ float g_Ht[(size_t)MT * HH];      // text hidden (26 MB)

// ---------------------------------------------------------------------------
// TF32 helpers
// ---------------------------------------------------------------------------
__device__ __forceinline__ uint32_t f2tf(float x) {
    uint32_t r;
    asm("cvt.rna.tf32.f32 %0, %1;" : "=r"(r) : "f"(x));
    return r;
}

__device__ __forceinline__ void mma_tf32(float* c,
    uint32_t a0, uint32_t a1, uint32_t a2, uint32_t a3,
    uint32_t b0, uint32_t b1)
{
    asm volatile(
        "mma.sync.aligned.m16n8k8.row.col.f32.tf32.tf32.f32 "
        "{%0,%1,%2,%3}, {%4,%5,%6,%7}, {%8,%9}, {%0,%1,%2,%3};\n"
        : "+f"(c[0]), "+f"(c[1]), "+f"(c[2]), "+f"(c[3])
        : "r"(a0), "r"(a1), "r"(a2), "r"(a3), "r"(b0), "r"(b1));
}

// Smem layout: element (k, x) lives at plane (k&3), offset x*4 + (k>>2).
// One uint4 read at [c][x*4] yields k = c, c+4, c+8, c+12 for row/col x —
// both k8-halves of a BK=16 stage in a single LDS.128.
__device__ __forceinline__ void mma_stage2(
    const uint32_t* __restrict__ Asb, const uint32_t* __restrict__ Bsb,
    int wrow, int wcol, int fr, int fc, float acc[4][4][4])
{
    const uint32_t* ab = Asb + fc * ASTR;
    const uint32_t* bb = Bsb + fc * ASTR;
    uint4 alo[4], ahi[4];
    #pragma unroll
    for (int mt = 0; mt < 4; mt++) {
        int m = wrow + mt * 16 + fr;
        alo[mt] = *(const uint4*)&ab[m * 4];
        ahi[mt] = *(const uint4*)&ab[(m + 8) * 4];
    }
    #pragma unroll
    for (int nt = 0; nt < 4; nt++) {
        int n = wcol + nt * 8 + fr;
        uint4 bq = *(const uint4*)&bb[n * 4];
        #pragma unroll
        for (int mt = 0; mt < 4; mt++) {
            mma_tf32(acc[mt][nt], alo[mt].x, ahi[mt].x, alo[mt].y, ahi[mt].y, bq.x, bq.y);
            mma_tf32(acc[mt][nt], alo[mt].z, ahi[mt].z, alo[mt].w, ahi[mt].w, bq.z, bq.w);
        }
    }
}

// Store staged registers into the interleaved layout.
// A slot (m, kq): values are k = kq*4+q  -> plane q, offset m*4+kq (4x STS.32, conflict-free)
// B slot (n, c):  values are k = c+4t    -> plane c, offset n*4+t  (1x STS.128, conflict-free)
__device__ __forceinline__ void sts_stage(
    uint32_t* Asb, uint32_t* Bsb,
    const int* amM, const int* amK, const int* bnN, const int* bcC,
    float aR[2][4], float bR[2][4])
{
    #pragma unroll
    for (int l = 0; l < 2; l++) {
        #pragma unroll
        for (int q = 0; q < 4; q++)
            Asb[q * ASTR + amM[l] * 4 + amK[l]] = f2tf(aR[l][q]);
        uint4 bb = make_uint4(f2tf(bR[l][0]), f2tf(bR[l][1]),
                              f2tf(bR[l][2]), f2tf(bR[l][3]));
        *(uint4*)&Bsb[bcC[l] * ASTR + bnN[l] * 4] = bb;
    }
}

// ---------------------------------------------------------------------------
// Grounding layer 1 (fused A-gen, tf32 tensor cores):
// H1[r,c] = relu((f_i⊙v_j)@Wp + Apre[i,c] + Cpre[j,c] + b1[c]), r = i*160+j.
// ---------------------------------------------------------------------------
__global__ __launch_bounds__(256, 2) void ground_h1_tc(
    const float* __restrict__ f, const float* __restrict__ v,
    const float* __restrict__ Wp, const float* __restrict__ b1)
{
    __shared__ uint32_t As[2][4 * ASTR];
    __shared__ uint32_t Bs[2][4 * ASTR];
    int tid = threadIdx.x;
    int lane = tid & 31, wid = tid >> 5;
    int wm = wid & 1, wn = wid >> 1;
    int wrow = wm * 64, wcol = wn * 32;
    int fr = lane >> 2, fc = lane & 3;
    int row0 = blockIdx.y * BM, col0 = blockIdx.x * BN;

    int amM[2], amK[2], bnN[2], bcC[2];
    size_t aF[2], aV[2];
    #pragma unroll
    for (int l = 0; l < 2; l++) {
        int idx = tid + l * 256;
        amM[l] = idx >> 2; amK[l] = idx & 3;
        int gr = row0 + amM[l];
        int gi = gr / MJ, gj = gr - gi * MJ;
        aF[l] = (size_t)gi * DD; aV[l] = (size_t)gj * DD;
        bnN[l] = idx & 127; bcC[l] = idx >> 7;
    }

    float aR[2][4], bR[2][4];
    #pragma unroll
    for (int l = 0; l < 2; l++) {
        float4 f4 = *(const float4*)&f[aF[l] + amK[l] * 4];
        float4 v4 = *(const float4*)&v[aV[l] + amK[l] * 4];
        aR[l][0] = f4.x * v4.x; aR[l][1] = f4.y * v4.y;
        aR[l][2] = f4.z * v4.z; aR[l][3] = f4.w * v4.w;
        #pragma unroll
        for (int t = 0; t < 4; t++)
            bR[l][t] = Wp[(size_t)(bcC[l] + 4 * t) * HH + col0 + bnN[l]];
    }

    float acc[4][4][4] = {};
    int p = 0;
    for (int kt = 0; kt < DD; kt += BK) {
        sts_stage(As[p], Bs[p], amM, amK, bnN, bcC, aR, bR);
        __syncthreads();
        int ktn = kt + BK;
        if (ktn < DD) {
            #pragma unroll
            for (int l = 0; l < 2; l++) {
                float4 f4 = *(const float4*)&f[aF[l] + ktn + amK[l] * 4];
                float4 v4 = *(const float4*)&v[aV[l] + ktn + amK[l] * 4];
                aR[l][0] = f4.x * v4.x; aR[l][1] = f4.y * v4.y;
                aR[l][2] = f4.z * v4.z; aR[l][3] = f4.w * v4.w;
                #pragma unroll
                for (int t = 0; t < 4; t++)
                    bR[l][t] = Wp[(size_t)(ktn + bcC[l] + 4 * t) * HH + col0 + bnN[l]];
            }
        }
        mma_stage2(As[p], Bs[p], wrow, wcol, fr, fc, acc);
        p ^= 1;
    }

    #pragma unroll
    for (int mt = 0; mt < 4; mt++) {
        #pragma unroll
        for (int h = 0; h < 2; h++) {
            int r = row0 + wrow + mt * 16 + fr + h * 8;
            int gi = r / MJ, gj = r - gi * MJ;
            const float* ap = &g_Apre[(size_t)gi * HH];
            const float* cp = &g_Cpre[(size_t)gj * HH];
            float* hp = &g_H1[(size_t)r * HH];
            #pragma unroll
            for (int nt = 0; nt < 4; nt++) {
                int c = col0 + wcol + nt * 8 + fc * 2;
                float x0 = acc[mt][nt][h * 2 + 0] + ap[c] + cp[c] + b1[c];
                float x1 = acc[mt][nt][h * 2 + 1] + ap[c + 1] + cp[c + 1] + b1[c + 1];
                *(float2*)&hp[c] = make_float2(fmaxf(x0, 0.f), fmaxf(x1, 0.f));
            }
        }
    }
}

// ---------------------------------------------------------------------------
// Text layer 1: g_Ht = relu(g_Xt @ tW1 + tb1). M = 6240, K = 3072, N = 1024.
// ---------------------------------------------------------------------------
__global__ __launch_bounds__(256, 2) void text1_tc(
    const float* __restrict__ W1, const float* __restrict__ b1)
{
    __shared__ uint32_t As[2][4 * ASTR];
    __shared__ uint32_t Bs[2][4 * ASTR];
    int tid = threadIdx.x;
    int lane = tid & 31, wid = tid >> 5;
    int wm = wid & 1, wn = wid >> 1;
    int wrow = wm * 64, wcol = wn * 32;
    int fr = lane >> 2, fc = lane & 3;
    int row0 = blockIdx.y * BM, col0 = blockIdx.x * BN;

    int amM[2], amK[2], bnN[2], bcC[2], aOK[2];
    size_t aBase[2];
    #pragma unroll
    for (int l = 0; l < 2; l++) {
        int idx = tid + l * 256;
        amM[l] = idx >> 2; amK[l] = idx & 3;
        int gr = row0 + amM[l];
        aOK[l] = (gr < MT);
        aBase[l] = (size_t)(aOK[l] ? gr : 0) * K3;
        bnN[l] = idx & 127; bcC[l] = idx >> 7;
    }

    float aR[2][4], bR[2][4];
    const float4 zero4 = make_float4(0.f, 0.f, 0.f, 0.f);
    #pragma unroll
    for (int l = 0; l < 2; l++) {
        float4 x4 = aOK[l] ? *(const float4*)&g_Xt[aBase[l] + amK[l] * 4] : zero4;
        aR[l][0] = x4.x; aR[l][1] = x4.y; aR[l][2] = x4.z; aR[l][3] = x4.w;
        #pragma unroll
        for (int t = 0; t < 4; t++)
            bR[l][t] = W1[(size_t)(bcC[l] + 4 * t) * HH + col0 + bnN[l]];
    }

    float acc[4][4][4] = {};
    int p = 0;
    for (int kt = 0; kt < K3; kt += BK) {
        sts_stage(As[p], Bs[p], amM, amK, bnN, bcC, aR, bR);
        __syncthreads();
        int ktn = kt + BK;
        if (ktn < K3) {
            #pragma unroll
            for (int l = 0; l < 2; l++) {
                float4 x4 = aOK[l] ? *(const float4*)&g_Xt[aBase[l] + ktn + amK[l] * 4] : zero4;
                aR[l][0] = x4.x; aR[l][1] = x4.y; aR[l][2] = x4.z; aR[l][3] = x4.w;
                #pragma unroll
                for (int t = 0; t < 4; t++)
                    bR[l][t] = W1[(size_t)(ktn + bcC[l] + 4 * t) * HH + col0 + bnN[l]];
            }
        }
        mma_stage2(As[p], Bs[p], wrow, wcol, fr, fc, acc);
        p ^= 1;
    }

    #pragma unroll
    for (int mt = 0; mt < 4; mt++) {
        #pragma unroll
        for (int h = 0; h < 2; h++) {
            int r = row0 + wrow + mt * 16 + fr + h * 8;
            if (r >= MT) continue;
            float* hp = &g_Ht[(size_t)r * HH];
            #pragma unroll
            for (int nt = 0; nt < 4; nt++) {
                int c = col0 + wcol + nt * 8 + fc * 2;
                float x0 = acc[mt][nt][h * 2 + 0] + b1[c];
                float x1 = acc[mt][nt][h * 2 + 1] + b1[c + 1];
                *(float2*)&hp[c] = make_float2(fmaxf(x0, 0.f), fmaxf(x1, 0.f));
            }
        }
    }
}

// ---------------------------------------------------------------------------
// Fused tail (tf32): out[r] = relu(H[r,:]@W2 + b2) @ W3 + b3 (optional mask).
// h_sel: 0 -> g_H1, 1 -> g_Ht. Deterministic reduction.
// ---------------------------------------------------------------------------
__global__ __launch_bounds__(256, 2) void tail_tc(
    int h_sel, const float* __restrict__ W2,
    const float* __restrict__ b2, const float* __restrict__ W3,
    const float* __restrict__ b3v, const float* __restrict__ sm,
    const float* __restrict__ im, float* __restrict__ outp,
    int M, int masked)
{
    const float* Hm = (h_sel == 0) ? g_H1 : g_Ht;
    __shared__ uint32_t As[2][4 * ASTR];
    __shared__ uint32_t Bs[2][4 * ASTR];
    __shared__ float red[BM * 16];
    int tid = threadIdx.x;
    int lane = tid & 31, wid = tid >> 5;
    int wm = wid & 1, wn = wid >> 1;
    int wrow = wm * 64, wcol = wn * 32;
    int fr = lane >> 2, fc = lane & 3;
    int row0 = blockIdx.x * BM;
    float rsum[4][2] = {};

    int amM[2], amK[2], bnN[2], bcC[2], aOK[2];
    size_t aBase[2];
    #pragma unroll
    for (int l = 0; l < 2; l++) {
        int idx = tid + l * 256;
        amM[l] = idx >> 2; amK[l] = idx & 3;
        int gr = row0 + amM[l];
        aOK[l] = (gr < M);
        aBase[l] = (size_t)(aOK[l] ? gr : 0) * HH;
        bnN[l] = idx & 127; bcC[l] = idx >> 7;
    }

    const float4 zero4 = make_float4(0.f, 0.f, 0.f, 0.f);
    int p = 0;
    for (int nc = 0; nc < HH; nc += BN) {
        float aR[2][4], bR[2][4];
        #pragma unroll
        for (int l = 0; l < 2; l++) {
            float4 x4 = aOK[l] ? *(const float4*)&Hm[aBase[l] + amK[l] * 4] : zero4;
            aR[l][0] = x4.x; aR[l][1] = x4.y; aR[l][2] = x4.z; aR[l][3] = x4.w;
            #pragma unroll
            for (int t = 0; t < 4; t++)
                bR[l][t] = W2[(size_t)(bcC[l] + 4 * t) * HH + nc + bnN[l]];
        }
        float acc[4][4][4] = {};
        for (int kt = 0; kt < HH; kt += BK) {
            sts_stage(As[p], Bs[p], amM, amK, bnN, bcC, aR, bR);
            __syncthreads();
            int ktn = kt + BK;
            if (ktn < HH) {
                #pragma unroll
                for (int l = 0; l < 2; l++) {
                    float4 x4 = aOK[l] ? *(const float4*)&Hm[aBase[l] + ktn + amK[l] * 4] : zero4;
                    aR[l][0] = x4.x; aR[l][1] = x4.y; aR[l][2] = x4.z; aR[l][3] = x4.w;
                    #pragma unroll
                    for (int t = 0; t < 4; t++)
                        bR[l][t] = W2[(size_t)(ktn + bcC[l] + 4 * t) * HH + nc + bnN[l]];
                }
            }
            mma_stage2(As[p], Bs[p], wrow, wcol, fr, fc, acc);
            p ^= 1;
        }
        #pragma unroll
        for (int mt = 0; mt < 4; mt++) {
            #pragma unroll
            for (int nt = 0; nt < 4; nt++) {
                int c = nc + wcol + nt * 8 + fc * 2;
                float w30 = W3[c], w31 = W3[c + 1];
                float b20 = b2[c], b21 = b2[c + 1];
                rsum[mt][0] += fmaxf(acc[mt][nt][0] + b20, 0.f) * w30
                             + fmaxf(acc[mt][nt][1] + b21, 0.f) * w31;
                rsum[mt][1] += fmaxf(acc[mt][nt][2] + b20, 0.f) * w30
                             + fmaxf(acc[mt][nt][3] + b21, 0.f) * w31;
            }
        }
    }

    #pragma unroll
    for (int mt = 0; mt < 4; mt++)
        #pragma unroll
        for (int h = 0; h < 2; h++) {
            int row = wrow + mt * 16 + fr + h * 8;
            red[row * 16 + wn * 4 + fc] = rsum[mt][h];
        }
    __syncthreads();
    if (tid < BM) {
        int r = row0 + tid;
        if (r < M) {
            float s = 0.f;
            #pragma unroll
            for (int t = 0; t < 16; t++) s += red[tid * 16 + t];
            s += b3v[0];
            if (masked) {
                int gi = r / MJ, gj = r - gi * MJ;
                s *= sm[gi] * im[gj];
            }
            outp[r] = s;
        }
    }
}

// ---------------------------------------------------------------------------
// Small SGEMM (fp32, 64x64 tile) for the two tiny pre-GEMMs f@Wf, v@Ws.
// c_sel: 0 -> g_Apre, 1 -> g_Cpre.
// ---------------------------------------------------------------------------
__global__ __launch_bounds__(256) void sgemm_small(
    const float* __restrict__ A, const float* __restrict__ Bm,
    int c_sel, int M, int N, int K)
{
    float* C = (c_sel == 0) ? g_Apre : g_Cpre;
    __shared__ __align__(16) float As[16][66];
    __shared__ __align__(16) float Bs[16][64];
    int tid = threadIdx.x;
    int tx = tid & 15, ty = tid >> 4;
    int row0 = blockIdx.y * 64, col0 = blockIdx.x * 64;
    float acc[4][4] = {};
    for (int kt = 0; kt < K; kt += 16) {
        #pragma unroll
        for (int l = 0; l < 4; l++) {
            int idx = tid + l * 256;
            int m = idx >> 4, kk = idx & 15;
            int gr = row0 + m;
            As[kk][m] = (gr < M) ? A[(size_t)gr * K + kt + kk] : 0.f;
        }
        #pragma unroll
        for (int l = 0; l < 4; l++) {
            int idx = tid + l * 256;
            int kk = idx >> 6, c = idx & 63;
            Bs[kk][c] = Bm[(size_t)(kt + kk) * N + col0 + c];
        }
        __syncthreads();
        #pragma unroll
        for (int kk = 0; kk < 16; kk++) {
            float av[4];
            #pragma unroll
            for (int i = 0; i < 4; i++) av[i] = As[kk][ty * 4 + i];
            float4 b4 = *(const float4*)&Bs[kk][tx * 4];
            float bv[4] = {b4.x, b4.y, b4.z, b4.w};
            #pragma unroll
            for (int i = 0; i < 4; i++)
                #pragma unroll
                for (int j = 0; j < 4; j++)
                    acc[i][j] += av[i] * bv[j];
        }
        __syncthreads();
    }
    #pragma unroll
    for (int i = 0; i < 4; i++) {
        int r = row0 + ty * 4 + i;
        if (r >= M) continue;
        #pragma unroll
        for (int j = 0; j < 4; j++)
            C[(size_t)r * N + col0 + tx * 4 + j] = acc[i][j];
    }
}

// ---------------------------------------------------------------------------
// Build text concat input: Xt[b*780+p] = [span[fi], span[si], span[fi]*span[si]]
// ---------------------------------------------------------------------------
__global__ void build_xt_kernel(const float* __restrict__ span)
{
    int r = blockIdx.x;
    int b = r / NPAIR, p = r - b * NPAIR;
    int n = 0, rem = p;
    while (rem >= (NS - 1 - n)) { rem -= (NS - 1 - n); n++; }
    int fi = n, si = n + 1 + rem;
    const float* a = span + ((size_t)b * NS + fi) * DD;
    const float* c = span + ((size_t)b * NS + si) * DD;
    float* x = g_Xt + (size_t)r * K3;
    for (int d = threadIdx.x; d < DD; d += blockDim.x) {
        float av = a[d], cv = c[d];
        x[d] = av;
        x[DD + d] = cv;
        x[2 * DD + d] = av * cv;
    }
}

// ---------------------------------------------------------------------------
// S[8][8] = chunk sums of 800 grounding scores; loss = bidirectional NCE.
// ---------------------------------------------------------------------------
__global__ void loss_kernel(const float* __restrict__ gsc, float* __restrict__ out0)
{
    __shared__ float S[64];
    __shared__ float red[256];
    int tid = threadIdx.x;
    int e = tid >> 2, q = tid & 3;
    float s = 0.f;
    const float* base = gsc + e * 800;
    for (int k = q; k < 800; k += 4) s += base[k];
    red[tid] = s;
    __syncthreads();
    if (q == 0) S[e] = red[tid] + red[tid + 1] + red[tid + 2] + red[tid + 3];
    __syncthreads();
    if (tid == 0) {
        float loss = 0.f;
        for (int a = 0; a < 8; a++) {
            float mx = -1e30f;
            for (int b = 0; b < 8; b++) mx = fmaxf(mx, S[a * 8 + b]);
            float se = 0.f;
            for (int b = 0; b < 8; b++) se += expf(S[a * 8 + b] - mx);
            float lse = mx + logf(se);
            for (int b = 0; b < 8; b++) loss -= (S[a * 8 + b] - lse);
        }
        for (int b = 0; b < 8; b++) {
            float mx = -1e30f;
            for (int a = 0; a < 8; a++) mx = fmaxf(mx, S[a * 8 + b]);
            float se = 0.f;
            for (int a = 0; a < 8; a++) se += expf(S[a * 8 + b] - mx);
            float lse = mx + logf(se);
            for (int a = 0; a < 8; a++) loss -= (S[a * 8 + b] - lse);
        }
        out0[0] = loss / 8.0f;
    }
}

extern "C" void kernel_launch(void* const* d_in, const int* in_sizes, int n_in,
                              void* d_out, int out_size)
{
    const float* span  = (const float*)d_in[0];
    const float* img   = (const float*)d_in[1];
    const float* smask = (const float*)d_in[2];
    const float* imask = (const float*)d_in[3];
    const float* tW1 = (const float*)d_in[4];
    const float* tb1 = (const float*)d_in[5];
    const float* tW2 = (const float*)d_in[6];
    const float* tb2 = (const float*)d_in[7];
    const float* tW3 = (const float*)d_in[8];
    const float* tb3 = (const float*)d_in[9];
    const float* gW1 = (const float*)d_in[10];
    const float* gb1 = (const float*)d_in[11];
    const float* gW2 = (const float*)d_in[12];
    const float* gb2 = (const float*)d_in[13];
    const float* gW3 = (const float*)d_in[14];
    const float* gb3 = (const float*)d_in[15];
    float* out = (float*)d_out;

    dim3 blk(256);

    // Grounding path
    sgemm_small<<<dim3(16, 5), blk>>>(span, gW1, 0, MI, HH, DD);
    sgemm_small<<<dim3(16, 3), blk>>>(img, gW1 + (size_t)DD * HH, 1, MJ, HH, DD);
    ground_h1_tc<<<dim3(HH / BN, MG / BM), blk>>>(span, img, gW1 + (size_t)2 * DD * HH, gb1);
    tail_tc<<<dim3(MG / BM), blk>>>(0, gW2, gb2, gW3, gb3, smask, imask, out + 1, MG, 1);

    // Text path
    build_xt_kernel<<<dim3(MT), blk>>>(span);
    text1_tc<<<dim3(HH / BN, (MT + BM - 1) / BM), blk>>>(tW1, tb1);
    tail_tc<<<dim3((MT + BM - 1) / BM), blk>>>(1, tW2, tb2, tW3, tb3,
                                               nullptr, nullptr, out + 1 + MG, MT, 0);

    // S and loss (reads masked grounding scores from out)
    loss_kernel<<<1, 256>>>(out + 1, out);
}

// round 11
// speedup vs baseline: 3.3758x; 1.0964x over previous
#include <cuda_runtime.h>
#include <cstdint>

#define DD 1024
#define HH 1024
#define NB 8
#define NS 40
#define NL 20
#define MI 320        // B*N rows of f
#define MJ 160        // B*L rows of v
#define MG 51200      // MI*MJ grounding pairs
#define NPAIR 780     // triu_indices(40, k=1)
#define MT 6240       // B*NPAIR text rows
#define K3 3072

#define BM 128
#define BN 128
#define BK 16
#define ASTR 520      // plane stride in u32: BM*4 + 8 (conflict-free chunks)

// Scratch (static device globals; no runtime allocation anywhere)
__device__ float    g_Apre[MI * HH];           // f @ Wf (fp32)
__device__ float    g_Cpre[MJ * HH];           // v @ Ws (fp32)
__device__ uint32_t g_H1[(size_t)MG * HH];     // grounding hidden (tf32 bits)
__device__ uint32_t g_Xt[(size_t)MT * K3];     // text concat input (tf32 bits)
__device__ uint32_t g_Ht[(size_t)MT * HH];     // text hidden (tf32 bits)
// Pre-transformed tf32 weights, tile-plane layout:
//   WT[((k/16)*4 + (k&3)) * (HH*4) + n*4 + ((k>>2)&3)] = tf32(W[k][n])
__device__ uint32_t g_WpT[DD * HH];
__device__ uint32_t g_W1T[(size_t)K3 * HH];
__device__ uint32_t g_W2gT[HH * HH];
__device__ uint32_t g_W2tT[HH * HH];

// ---------------------------------------------------------------------------
// TF32 helpers
// ---------------------------------------------------------------------------
__device__ __forceinline__ uint32_t f2tf(float x) {
    uint32_t r;
    asm("cvt.rna.tf32.f32 %0, %1;" : "=r"(r) : "f"(x));
    return r;
}

__device__ __forceinline__ void mma_tf32(float* c,
    uint32_t a0, uint32_t a1, uint32_t a2, uint32_t a3,
    uint32_t b0, uint32_t b1)
{
    asm volatile(
        "mma.sync.aligned.m16n8k8.row.col.f32.tf32.tf32.f32 "
        "{%0,%1,%2,%3}, {%4,%5,%6,%7}, {%8,%9}, {%0,%1,%2,%3};\n"
        : "+f"(c[0]), "+f"(c[1]), "+f"(c[2]), "+f"(c[3])
        : "r"(a0), "r"(a1), "r"(a2), "r"(a3), "r"(b0), "r"(b1));
}

// Weight transform: W[K x 1024] fp32 -> tile-plane tf32 layout.
// out[id], id = ((tile*4 + c)*1024 + n)*4 + t, holds tf32(W[tile*16 + c + 4t][n]).
__global__ void wconv_kernel(const float* __restrict__ W, int dst_sel, int K)
{
    uint32_t* out = (dst_sel == 0) ? g_WpT : (dst_sel == 1) ? g_W1T
                  : (dst_sel == 2) ? g_W2gT : g_W2tT;
    int id = blockIdx.x * 256 + threadIdx.x;
    if (id >= K * 1024) return;
    int t = id & 3, n = (id >> 2) & 1023;
    int c = (id >> 12) & 3, tile = id >> 14;
    int k = tile * 16 + c + 4 * t;
    out[id] = f2tf(W[(size_t)k * 1024 + n]);
}

// Smem layout: element (k, x) lives at plane (k&3), offset x*4 + (k>>2).
// One uint4 read at [c][x*4] yields k = c, c+4, c+8, c+12 for row/col x.
__device__ __forceinline__ void mma_stage2(
    const uint32_t* __restrict__ Asb, const uint32_t* __restrict__ Bsb,
    int wrow, int wcol, int fr, int fc, float acc[4][4][4])
{
    const uint32_t* ab = Asb + fc * ASTR;
    const uint32_t* bb = Bsb + fc * ASTR;
    uint4 alo[4], ahi[4];
    #pragma unroll
    for (int mt = 0; mt < 4; mt++) {
        int m = wrow + mt * 16 + fr;
        alo[mt] = *(const uint4*)&ab[m * 4];
        ahi[mt] = *(const uint4*)&ab[(m + 8) * 4];
    }
    #pragma unroll
    for (int nt = 0; nt < 4; nt++) {
        int n = wcol + nt * 8 + fr;
        uint4 bq = *(const uint4*)&bb[n * 4];
        #pragma unroll
        for (int mt = 0; mt < 4; mt++) {
            mma_tf32(acc[mt][nt], alo[mt].x, ahi[mt].x, alo[mt].y, ahi[mt].y, bq.x, bq.y);
            mma_tf32(acc[mt][nt], alo[mt].z, ahi[mt].z, alo[mt].w, ahi[mt].w, bq.z, bq.w);
        }
    }
}

// Staging stores (pre-converted u32 A + B). A: 4 STS.32 planes; B: 1 STS.128.
__device__ __forceinline__ void sts_stage_u32(
    uint32_t* Asb, uint32_t* Bsb,
    const int* amM, const int* amK, const int* bnN, const int* bcC,
    const uint4* aU, const uint4* bU)
{
    #pragma unroll
    for (int l = 0; l < 2; l++) {
        Asb[0 * ASTR + amM[l] * 4 + amK[l]] = aU[l].x;
        Asb[1 * ASTR + amM[l] * 4 + amK[l]] = aU[l].y;
        Asb[2 * ASTR + amM[l] * 4 + amK[l]] = aU[l].z;
        Asb[3 * ASTR + amM[l] * 4 + amK[l]] = aU[l].w;
        *(uint4*)&Bsb[bcC[l] * ASTR + bnN[l] * 4] = bU[l];
    }
}

// ---------------------------------------------------------------------------
// Grounding layer 1 (fused A-gen, tf32 tensor cores):
// H1[r,c] = relu((f_i⊙v_j)@Wp + Apre[i,c] + Cpre[j,c] + b1[c]), r = i*160+j.
// A converted in-loop (new data); B loaded pre-transformed from g_WpT.
// ---------------------------------------------------------------------------
__global__ __launch_bounds__(256, 2) void ground_h1_tc(
    const float* __restrict__ f, const float* __restrict__ v,
    const float* __restrict__ b1)
{
    __shared__ uint32_t As[2][4 * ASTR];
    __shared__ uint32_t Bs[2][4 * ASTR];
    int tid = threadIdx.x;
    int lane = tid & 31, wid = tid >> 5;
    int wm = wid & 1, wn = wid >> 1;
    int wrow = wm * 64, wcol = wn * 32;
    int fr = lane >> 2, fc = lane & 3;
    int row0 = blockIdx.y * BM, col0 = blockIdx.x * BN;

    int amM[2], amK[2], bnN[2], bcC[2];
    size_t aF[2], aV[2], bOff[2];
    #pragma unroll
    for (int l = 0; l < 2; l++) {
        int idx = tid + l * 256;
        amM[l] = idx >> 2; amK[l] = idx & 3;
        int gr = row0 + amM[l];
        int gi = gr / MJ, gj = gr - gi * MJ;
        aF[l] = (size_t)gi * DD; aV[l] = (size_t)gj * DD;
        bnN[l] = idx & 127; bcC[l] = idx >> 7;
        bOff[l] = (size_t)bcC[l] * (HH * 4) + (size_t)(col0 + bnN[l]) * 4;
    }

    uint4 aU[2], bU[2];
    #pragma unroll
    for (int l = 0; l < 2; l++) {
        float4 f4 = *(const float4*)&f[aF[l] + amK[l] * 4];
        float4 v4 = *(const float4*)&v[aV[l] + amK[l] * 4];
        aU[l] = make_uint4(f2tf(f4.x * v4.x), f2tf(f4.y * v4.y),
                           f2tf(f4.z * v4.z), f2tf(f4.w * v4.w));
        bU[l] = *(const uint4*)&g_WpT[bOff[l]];
    }

    float acc[4][4][4] = {};
    int p = 0;
    for (int kt = 0; kt < DD; kt += BK) {
        sts_stage_u32(As[p], Bs[p], amM, amK, bnN, bcC, aU, bU);
        __syncthreads();
        int ktn = kt + BK;
        if (ktn < DD) {
            #pragma unroll
            for (int l = 0; l < 2; l++) {
                float4 f4 = *(const float4*)&f[aF[l] + ktn + amK[l] * 4];
                float4 v4 = *(const float4*)&v[aV[l] + ktn + amK[l] * 4];
                aU[l] = make_uint4(f2tf(f4.x * v4.x), f2tf(f4.y * v4.y),
                                   f2tf(f4.z * v4.z), f2tf(f4.w * v4.w));
                bU[l] = *(const uint4*)&g_WpT[(size_t)(ktn >> 4) * (HH * 16) + bOff[l]];
            }
        }
        mma_stage2(As[p], Bs[p], wrow, wcol, fr, fc, acc);
        p ^= 1;
    }

    #pragma unroll
    for (int mt = 0; mt < 4; mt++) {
        #pragma unroll
        for (int h = 0; h < 2; h++) {
            int r = row0 + wrow + mt * 16 + fr + h * 8;
            int gi = r / MJ, gj = r - gi * MJ;
            const float* ap = &g_Apre[(size_t)gi * HH];
            const float* cp = &g_Cpre[(size_t)gj * HH];
            uint32_t* hp = &g_H1[(size_t)r * HH];
            #pragma unroll
            for (int nt = 0; nt < 4; nt++) {
                int c = col0 + wcol + nt * 8 + fc * 2;
                float x0 = acc[mt][nt][h * 2 + 0] + ap[c] + cp[c] + b1[c];
                float x1 = acc[mt][nt][h * 2 + 1] + ap[c + 1] + cp[c + 1] + b1[c + 1];
                uint2 w = make_uint2(f2tf(fmaxf(x0, 0.f)), f2tf(fmaxf(x1, 0.f)));
                *(uint2*)&hp[c] = w;
            }
        }
    }
}

// ---------------------------------------------------------------------------
// Text layer 1: g_Ht = relu(g_Xt @ tW1 + tb1). A pre-tf32, B pre-transformed.
// ---------------------------------------------------------------------------
__global__ __launch_bounds__(256, 2) void text1_tc(const float* __restrict__ b1)
{
    __shared__ uint32_t As[2][4 * ASTR];
    __shared__ uint32_t Bs[2][4 * ASTR];
    int tid = threadIdx.x;
    int lane = tid & 31, wid = tid >> 5;
    int wm = wid & 1, wn = wid >> 1;
    int wrow = wm * 64, wcol = wn * 32;
    int fr = lane >> 2, fc = lane & 3;
    int row0 = blockIdx.y * BM, col0 = blockIdx.x * BN;

    int amM[2], amK[2], bnN[2], bcC[2], aOK[2];
    size_t aBase[2], bOff[2];
    #pragma unroll
    for (int l = 0; l < 2; l++) {
        int idx = tid + l * 256;
        amM[l] = idx >> 2; amK[l] = idx & 3;
        int gr = row0 + amM[l];
        aOK[l] = (gr < MT);
        aBase[l] = (size_t)(aOK[l] ? gr : 0) * K3;
        bnN[l] = idx & 127; bcC[l] = idx >> 7;
        bOff[l] = (size_t)bcC[l] * (HH * 4) + (size_t)(col0 + bnN[l]) * 4;
    }

    const uint4 zero4 = make_uint4(0, 0, 0, 0);
    uint4 aU[2], bU[2];
    #pragma unroll
    for (int l = 0; l < 2; l++) {
        aU[l] = aOK[l] ? *(const uint4*)&g_Xt[aBase[l] + amK[l] * 4] : zero4;
        bU[l] = *(const uint4*)&g_W1T[bOff[l]];
    }

    float acc[4][4][4] = {};
    int p = 0;
    for (int kt = 0; kt < K3; kt += BK) {
        sts_stage_u32(As[p], Bs[p], amM, amK, bnN, bcC, aU, bU);
        __syncthreads();
        int ktn = kt + BK;
        if (ktn < K3) {
            #pragma unroll
            for (int l = 0; l < 2; l++) {
                aU[l] = aOK[l] ? *(const uint4*)&g_Xt[aBase[l] + ktn + amK[l] * 4] : zero4;
                bU[l] = *(const uint4*)&g_W1T[(size_t)(ktn >> 4) * (HH * 16) + bOff[l]];
            }
        }
        mma_stage2(As[p], Bs[p], wrow, wcol, fr, fc, acc);
        p ^= 1;
    }

    #pragma unroll
    for (int mt = 0; mt < 4; mt++) {
        #pragma unroll
        for (int h = 0; h < 2; h++) {
            int r = row0 + wrow + mt * 16 + fr + h * 8;
            if (r >= MT) continue;
            uint32_t* hp = &g_Ht[(size_t)r * HH];
            #pragma unroll
            for (int nt = 0; nt < 4; nt++) {
                int c = col0 + wcol + nt * 8 + fc * 2;
                float x0 = acc[mt][nt][h * 2 + 0] + b1[c];
                float x1 = acc[mt][nt][h * 2 + 1] + b1[c + 1];
                uint2 w = make_uint2(f2tf(fmaxf(x0, 0.f)), f2tf(fmaxf(x1, 0.f)));
                *(uint2*)&hp[c] = w;
            }
        }
    }
}

// ---------------------------------------------------------------------------
// Fused tail (tf32): out[r] = relu(H[r,:]@W2 + b2) @ W3 + b3 (optional mask).
// h_sel: 0 -> g_H1/g_W2gT, 1 -> g_Ht/g_W2tT. A and B both pre-tf32.
// ---------------------------------------------------------------------------
__global__ __launch_bounds__(256, 2) void tail_tc(
    int h_sel, const float* __restrict__ b2, const float* __restrict__ W3,
    const float* __restrict__ b3v, const float* __restrict__ sm,
    const float* __restrict__ im, float* __restrict__ outp,
    int M, int masked)
{
    const uint32_t* Hm = (h_sel == 0) ? g_H1 : g_Ht;
    const uint32_t* W2T = (h_sel == 0) ? g_W2gT : g_W2tT;
    __shared__ uint32_t As[2][4 * ASTR];
    __shared__ uint32_t Bs[2][4 * ASTR];
    __shared__ float red[BM * 16];
    int tid = threadIdx.x;
    int lane = tid & 31, wid = tid >> 5;
    int wm = wid & 1, wn = wid >> 1;
    int wrow = wm * 64, wcol = wn * 32;
    int fr = lane >> 2, fc = lane & 3;
    int row0 = blockIdx.x * BM;
    float rsum[4][2] = {};

    int amM[2], amK[2], bnN[2], bcC[2], aOK[2];
    size_t aBase[2], bCol[2];
    #pragma unroll
    for (int l = 0; l < 2; l++) {
        int idx = tid + l * 256;
        amM[l] = idx >> 2; amK[l] = idx & 3;
        int gr = row0 + amM[l];
        aOK[l] = (gr < M);
        aBase[l] = (size_t)(aOK[l] ? gr : 0) * HH;
        bnN[l] = idx & 127; bcC[l] = idx >> 7;
        bCol[l] = (size_t)bcC[l] * (HH * 4);
    }

    const uint4 zero4 = make_uint4(0, 0, 0, 0);
    int p = 0;
    for (int nc = 0; nc < HH; nc += BN) {
        uint4 aU[2], bU[2];
        #pragma unroll
        for (int l = 0; l < 2; l++) {
            aU[l] = aOK[l] ? *(const uint4*)&Hm[aBase[l] + amK[l] * 4] : zero4;
            bU[l] = *(const uint4*)&W2T[bCol[l] + (size_t)(nc + bnN[l]) * 4];
        }
        float acc[4][4][4] = {};
        for (int kt = 0; kt < HH; kt += BK) {
            sts_stage_u32(As[p], Bs[p], amM, amK, bnN, bcC, aU, bU);
            __syncthreads();
            int ktn = kt + BK;
            if (ktn < HH) {
                #pragma unroll
                for (int l = 0; l < 2; l++) {
                    aU[l] = aOK[l] ? *(const uint4*)&Hm[aBase[l] + ktn + amK[l] * 4] : zero4;
                    bU[l] = *(const uint4*)&W2T[(size_t)(ktn >> 4) * (HH * 16) + bCol[l]
                                                + (size_t)(nc + bnN[l]) * 4];
                }
            }
            mma_stage2(As[p], Bs[p], wrow, wcol, fr, fc, acc);
            p ^= 1;
        }
        #pragma unroll
        for (int mt = 0; mt < 4; mt++) {
            #pragma unroll
            for (int nt = 0; nt < 4; nt++) {
                int c = nc + wcol + nt * 8 + fc * 2;
                float w30 = W3[c], w31 = W3[c + 1];
                float b20 = b2[c], b21 = b2[c + 1];
                rsum[mt][0] += fmaxf(acc[mt][nt][0] + b20, 0.f) * w30
                             + fmaxf(acc[mt][nt][1] + b21, 0.f) * w31;
                rsum[mt][1] += fmaxf(acc[mt][nt][2] + b20, 0.f) * w30
                             + fmaxf(acc[mt][nt][3] + b21, 0.f) * w31;
            }
        }
    }

    #pragma unroll
    for (int mt = 0; mt < 4; mt++)
        #pragma unroll
        for (int h = 0; h < 2; h++) {
            int row = wrow + mt * 16 + fr + h * 8;
            red[row * 16 + wn * 4 + fc] = rsum[mt][h];
        }
    __syncthreads();
    if (tid < BM) {
        int r = row0 + tid;
        if (r < M) {
            float s = 0.f;
            #pragma unroll
            for (int t = 0; t < 16; t++) s += red[tid * 16 + t];
            s += b3v[0];
            if (masked) {
                int gi = r / MJ, gj = r - gi * MJ;
                s *= sm[gi] * im[gj];
            }
            outp[r] = s;
        }
    }
}

// ---------------------------------------------------------------------------
// Small SGEMM (fp32, 64x64 tile) for the two tiny pre-GEMMs f@Wf, v@Ws.
// c_sel: 0 -> g_Apre, 1 -> g_Cpre.
// ---------------------------------------------------------------------------
__global__ __launch_bounds__(256) void sgemm_small(
    const float* __restrict__ A, const float* __restrict__ Bm,
    int c_sel, int M, int N, int K)
{
    float* C = (c_sel == 0) ? g_Apre : g_Cpre;
    __shared__ __align__(16) float As[16][66];
    __shared__ __align__(16) float Bs[16][64];
    int tid = threadIdx.x;
    int tx = tid & 15, ty = tid >> 4;
    int row0 = blockIdx.y * 64, col0 = blockIdx.x * 64;
    float acc[4][4] = {};
    for (int kt = 0; kt < K; kt += 16) {
        #pragma unroll
        for (int l = 0; l < 4; l++) {
            int idx = tid + l * 256;
            int m = idx >> 4, kk = idx & 15;
            int gr = row0 + m;
            As[kk][m] = (gr < M) ? A[(size_t)gr * K + kt + kk] : 0.f;
        }
        #pragma unroll
        for (int l = 0; l < 4; l++) {
            int idx = tid + l * 256;
            int kk = idx >> 6, c = idx & 63;
            Bs[kk][c] = Bm[(size_t)(kt + kk) * N + col0 + c];
        }
        __syncthreads();
        #pragma unroll
        for (int kk = 0; kk < 16; kk++) {
            float av[4];
            #pragma unroll
            for (int i = 0; i < 4; i++) av[i] = As[kk][ty * 4 + i];
            float4 b4 = *(const float4*)&Bs[kk][tx * 4];
            float bv[4] = {b4.x, b4.y, b4.z, b4.w};
            #pragma unroll
            for (int i = 0; i < 4; i++)
                #pragma unroll
                for (int j = 0; j < 4; j++)
                    acc[i][j] += av[i] * bv[j];
        }
        __syncthreads();
    }
    #pragma unroll
    for (int i = 0; i < 4; i++) {
        int r = row0 + ty * 4 + i;
        if (r >= M) continue;
        #pragma unroll
        for (int j = 0; j < 4; j++)
            C[(size_t)r * N + col0 + tx * 4 + j] = acc[i][j];
    }
}

// ---------------------------------------------------------------------------
// Build text concat input (tf32 bits):
// Xt[b*780+p] = [span[fi], span[si], span[fi]*span[si]]
// ---------------------------------------------------------------------------
__global__ void build_xt_kernel(const float* __restrict__ span)
{
    int r = blockIdx.x;
    int b = r / NPAIR, p = r - b * NPAIR;
    int n = 0, rem = p;
    while (rem >= (NS - 1 - n)) { rem -= (NS - 1 - n); n++; }
    int fi = n, si = n + 1 + rem;
    const float* a = span + ((size_t)b * NS + fi) * DD;
    const float* c = span + ((size_t)b * NS + si) * DD;
    uint32_t* x = g_Xt + (size_t)r * K3;
    for (int d = threadIdx.x; d < DD; d += blockDim.x) {
        float av = a[d], cv = c[d];
        x[d] = f2tf(av);
        x[DD + d] = f2tf(cv);
        x[2 * DD + d] = f2tf(av * cv);
    }
}

// ---------------------------------------------------------------------------
// S[8][8] = chunk sums of 800 grounding scores; loss = bidirectional NCE.
// ---------------------------------------------------------------------------
__global__ void loss_kernel(const float* __restrict__ gsc, float* __restrict__ out0)
{
    __shared__ float S[64];
    __shared__ float red[256];
    int tid = threadIdx.x;
    int e = tid >> 2, q = tid & 3;
    float s = 0.f;
    const float* base = gsc + e * 800;
    for (int k = q; k < 800; k += 4) s += base[k];
    red[tid] = s;
    __syncthreads();
    if (q == 0) S[e] = red[tid] + red[tid + 1] + red[tid + 2] + red[tid + 3];
    __syncthreads();
    if (tid == 0) {
        float loss = 0.f;
        for (int a = 0; a < 8; a++) {
            float mx = -1e30f;
            for (int b = 0; b < 8; b++) mx = fmaxf(mx, S[a * 8 + b]);
            float se = 0.f;
            for (int b = 0; b < 8; b++) se += expf(S[a * 8 + b] - mx);
            float lse = mx + logf(se);
            for (int b = 0; b < 8; b++) loss -= (S[a * 8 + b] - lse);
        }
        for (int b = 0; b < 8; b++) {
            float mx = -1e30f;
            for (int a = 0; a < 8; a++) mx = fmaxf(mx, S[a * 8 + b]);
            float se = 0.f;
            for (int a = 0; a < 8; a++) se += expf(S[a * 8 + b] - mx);
            float lse = mx + logf(se);
            for (int a = 0; a < 8; a++) loss -= (S[a * 8 + b] - lse);
        }
        out0[0] = loss / 8.0f;
    }
}

extern "C" void kernel_launch(void* const* d_in, const int* in_sizes, int n_in,
                              void* d_out, int out_size)
{
    const float* span  = (const float*)d_in[0];
    const float* img   = (const float*)d_in[1];
    const float* smask = (const float*)d_in[2];
    const float* imask = (const float*)d_in[3];
    const float* tW1 = (const float*)d_in[4];
    const float* tb1 = (const float*)d_in[5];
    const float* tW2 = (const float*)d_in[6];
    const float* tb2 = (const float*)d_in[7];
    const float* tW3 = (const float*)d_in[8];
    const float* tb3 = (const float*)d_in[9];
    const float* gW1 = (const float*)d_in[10];
    const float* gb1 = (const float*)d_in[11];
    const float* gW2 = (const float*)d_in[12];
    const float* gb2 = (const float*)d_in[13];
    const float* gW3 = (const float*)d_in[14];
    const float* gb3 = (const float*)d_in[15];
    float* out = (float*)d_out;

    dim3 blk(256);

    // Weight pre-transforms (tf32, tile-plane layout)
    wconv_kernel<<<(DD * 1024 + 255) / 256, blk>>>(gW1 + (size_t)2 * DD * HH, 0, DD);
    wconv_kernel<<<(K3 * 1024 + 255) / 256, blk>>>(tW1, 1, K3);
    wconv_kernel<<<(HH * 1024 + 255) / 256, blk>>>(gW2, 2, HH);
    wconv_kernel<<<(HH * 1024 + 255) / 256, blk>>>(tW2, 3, HH);

    // Grounding path
    sgemm_small<<<dim3(16, 5), blk>>>(span, gW1, 0, MI, HH, DD);
    sgemm_small<<<dim3(16, 3), blk>>>(img, gW1 + (size_t)DD * HH, 1, MJ, HH, DD);
    ground_h1_tc<<<dim3(HH / BN, MG / BM), blk>>>(span, img, gb1);
    tail_tc<<<dim3(MG / BM), blk>>>(0, gb2, gW3, gb3, smask, imask, out + 1, MG, 1);

    // Text path
    build_xt_kernel<<<dim3(MT), blk>>>(span);
    text1_tc<<<dim3(HH / BN, (MT + BM - 1) / BM), blk>>>(tb1);
    tail_tc<<<dim3((MT + BM - 1) / BM), blk>>>(1, tb2, tW3, tb3,
                                               nullptr, nullptr, out + 1 + MG, MT, 0);

    // S and loss (reads masked grounding scores from out)
    loss_kernel<<<1, 256>>>(out + 1, out);
}

// round 13
// speedup vs baseline: 4.0399x; 1.1967x over previous
#include <cuda_runtime.h>
#include <cstdint>

#define DD 1024
#define HH 1024
#define NB 8
#define NS 40
#define NL 20
#define MI 320        // B*N rows of f
#define MJ 160        // B*L rows of v
#define MG 51200      // MI*MJ grounding pairs
#define NPAIR 780     // triu_indices(40, k=1)
#define MT 6240       // B*NPAIR text rows
#define K3 3072

#define BM 128
#define BN 128
#define BK 16
#define ASTR 520      // plane stride in u32: BM*4 + 8 (conflict-free chunks)

// Scratch (static device globals; no runtime allocation anywhere)
__device__ float    g_Apre[MI * HH];           // f @ Wf (fp32)
__device__ float    g_Cpre[MJ * HH];           // v @ Ws (fp32)
__device__ uint32_t g_H1[(size_t)MG * HH];     // grounding hidden (tf32 bits)
__device__ uint32_t g_Xt[(size_t)MT * K3];     // text concat input (tf32 bits)
__device__ uint32_t g_Ht[(size_t)MT * HH];     // text hidden (tf32 bits)
// Pre-transformed tf32 weights, tile-plane layout:
//   WT[((k/16)*4 + (k&3)) * (HH*4) + n*4 + ((k>>2)&3)] = tf32(W[k][n])
__device__ uint32_t g_WpT[DD * HH];
__device__ uint32_t g_W1T[(size_t)K3 * HH];
__device__ uint32_t g_W2gT[HH * HH];
__device__ uint32_t g_W2tT[HH * HH];

// ---------------------------------------------------------------------------
// TF32 helpers
// ---------------------------------------------------------------------------
__device__ __forceinline__ uint32_t f2tf(float x) {
    uint32_t r;
    asm("cvt.rna.tf32.f32 %0, %1;" : "=r"(r) : "f"(x));
    return r;
}

__device__ __forceinline__ void mma_tf32(float* c,
    uint32_t a0, uint32_t a1, uint32_t a2, uint32_t a3,
    uint32_t b0, uint32_t b1)
{
    asm volatile(
        "mma.sync.aligned.m16n8k8.row.col.f32.tf32.tf32.f32 "
        "{%0,%1,%2,%3}, {%4,%5,%6,%7}, {%8,%9}, {%0,%1,%2,%3};\n"
        : "+f"(c[0]), "+f"(c[1]), "+f"(c[2]), "+f"(c[3])
        : "r"(a0), "r"(a1), "r"(a2), "r"(a3), "r"(b0), "r"(b1));
}

// Weight transform: W[K x 1024] fp32 -> tile-plane tf32 layout.
// out[id], id = ((tile*4 + c)*1024 + n)*4 + t, holds tf32(W[tile*16 + c + 4t][n]).
__global__ void wconv_kernel(const float* __restrict__ W, int dst_sel, int K)
{
    uint32_t* out = (dst_sel == 0) ? g_WpT : (dst_sel == 1) ? g_W1T
                  : (dst_sel == 2) ? g_W2gT : g_W2tT;
    int id = blockIdx.x * 256 + threadIdx.x;
    if (id >= K * 1024) return;
    int t = id & 3, n = (id >> 2) & 1023;
    int c = (id >> 12) & 3, tile = id >> 14;
    int k = tile * 16 + c + 4 * t;
    out[id] = f2tf(W[(size_t)k * 1024 + n]);
}

// Smem layout: element (k, x) lives at plane (k&3), offset x*4 + (k>>2).
// One uint4 read at [c][x*4] yields k = c, c+4, c+8, c+12 for row/col x.
__device__ __forceinline__ void mma_stage2(
    const uint32_t* __restrict__ Asb, const uint32_t* __restrict__ Bsb,
    int wrow, int wcol, int fr, int fc, float acc[4][4][4])
{
    const uint32_t* ab = Asb + fc * ASTR;
    const uint32_t* bb = Bsb + fc * ASTR;
    uint4 alo[4], ahi[4];
    #pragma unroll
    for (int mt = 0; mt < 4; mt++) {
        int m = wrow + mt * 16 + fr;
        alo[mt] = *(const uint4*)&ab[m * 4];
        ahi[mt] = *(const uint4*)&ab[(m + 8) * 4];
    }
    #pragma unroll
    for (int nt = 0; nt < 4; nt++) {
        int n = wcol + nt * 8 + fr;
        uint4 bq = *(const uint4*)&bb[n * 4];
        #pragma unroll
        for (int mt = 0; mt < 4; mt++) {
            mma_tf32(acc[mt][nt], alo[mt].x, ahi[mt].x, alo[mt].y, ahi[mt].y, bq.x, bq.y);
            mma_tf32(acc[mt][nt], alo[mt].z, ahi[mt].z, alo[mt].w, ahi[mt].w, bq.z, bq.w);
        }
    }
}

// Staging stores (pre-converted u32 A + B). A: 4 STS.32 planes; B: 1 STS.128.
__device__ __forceinline__ void sts_stage_u32(
    uint32_t* Asb, uint32_t* Bsb,
    const int* amM, const int* amK, const int* bnN, const int* bcC,
    const uint4* aU, const uint4* bU)
{
    #pragma unroll
    for (int l = 0; l < 2; l++) {
        Asb[0 * ASTR + amM[l] * 4 + amK[l]] = aU[l].x;
        Asb[1 * ASTR + amM[l] * 4 + amK[l]] = aU[l].y;
        Asb[2 * ASTR + amM[l] * 4 + amK[l]] = aU[l].z;
        Asb[3 * ASTR + amM[l] * 4 + amK[l]] = aU[l].w;
        *(uint4*)&Bsb[bcC[l] * ASTR + bnN[l] * 4] = bU[l];
    }
}

// ---------------------------------------------------------------------------
// Grounding layer 1 (fused A-gen, tf32 tensor cores):
// H1[r,c] = relu((f_i⊙v_j)@Wp + Apre[i,c] + Cpre[j,c] + b1[c]), r = i*160+j.
// ---------------------------------------------------------------------------
__global__ __launch_bounds__(256, 2) void ground_h1_tc(
    const float* __restrict__ f, const float* __restrict__ v,
    const float* __restrict__ b1)
{
    __shared__ uint32_t As[2][4 * ASTR];
    __shared__ uint32_t Bs[2][4 * ASTR];
    int tid = threadIdx.x;
    int lane = tid & 31, wid = tid >> 5;
    int wm = wid & 1, wn = wid >> 1;
    int wrow = wm * 64, wcol = wn * 32;
    int fr = lane >> 2, fc = lane & 3;
    int row0 = blockIdx.y * BM, col0 = blockIdx.x * BN;

    int amM[2], amK[2], bnN[2], bcC[2];
    size_t aF[2], aV[2], bOff[2];
    #pragma unroll
    for (int l = 0; l < 2; l++) {
        int idx = tid + l * 256;
        amM[l] = idx >> 2; amK[l] = idx & 3;
        int gr = row0 + amM[l];
        int gi = gr / MJ, gj = gr - gi * MJ;
        aF[l] = (size_t)gi * DD; aV[l] = (size_t)gj * DD;
        bnN[l] = idx & 127; bcC[l] = idx >> 7;
        bOff[l] = (size_t)bcC[l] * (HH * 4) + (size_t)(col0 + bnN[l]) * 4;
    }

    uint4 aU[2], bU[2];
    #pragma unroll
    for (int l = 0; l < 2; l++) {
        float4 f4 = *(const float4*)&f[aF[l] + amK[l] * 4];
        float4 v4 = *(const float4*)&v[aV[l] + amK[l] * 4];
        aU[l] = make_uint4(f2tf(f4.x * v4.x), f2tf(f4.y * v4.y),
                           f2tf(f4.z * v4.z), f2tf(f4.w * v4.w));
        bU[l] = *(const uint4*)&g_WpT[bOff[l]];
    }

    float acc[4][4][4] = {};
    int p = 0;
    for (int kt = 0; kt < DD; kt += BK) {
        sts_stage_u32(As[p], Bs[p], amM, amK, bnN, bcC, aU, bU);
        __syncthreads();
        int ktn = kt + BK;
        if (ktn < DD) {
            #pragma unroll
            for (int l = 0; l < 2; l++) {
                float4 f4 = *(const float4*)&f[aF[l] + ktn + amK[l] * 4];
                float4 v4 = *(const float4*)&v[aV[l] + ktn + amK[l] * 4];
                aU[l] = make_uint4(f2tf(f4.x * v4.x), f2tf(f4.y * v4.y),
                                   f2tf(f4.z * v4.z), f2tf(f4.w * v4.w));
                bU[l] = *(const uint4*)&g_WpT[(size_t)(ktn >> 4) * (HH * 16) + bOff[l]];
            }
        }
        mma_stage2(As[p], Bs[p], wrow, wcol, fr, fc, acc);
        p ^= 1;
    }

    #pragma unroll
    for (int mt = 0; mt < 4; mt++) {
        #pragma unroll
        for (int h = 0; h < 2; h++) {
            int r = row0 + wrow + mt * 16 + fr + h * 8;
            int gi = r / MJ, gj = r - gi * MJ;
            const float* ap = &g_Apre[(size_t)gi * HH];
            const float* cp = &g_Cpre[(size_t)gj * HH];
            uint32_t* hp = &g_H1[(size_t)r * HH];
            #pragma unroll
            for (int nt = 0; nt < 4; nt++) {
                int c = col0 + wcol + nt * 8 + fc * 2;
                float x0 = acc[mt][nt][h * 2 + 0] + ap[c] + cp[c] + b1[c];
                float x1 = acc[mt][nt][h * 2 + 1] + ap[c + 1] + cp[c + 1] + b1[c + 1];
                uint2 w = make_uint2(f2tf(fmaxf(x0, 0.f)), f2tf(fmaxf(x1, 0.f)));
                *(uint2*)&hp[c] = w;
            }
        }
    }
}

// ---------------------------------------------------------------------------
// Text layer 1: g_Ht = relu(g_Xt @ tW1 + tb1). A pre-tf32, B pre-transformed.
// ---------------------------------------------------------------------------
__global__ __launch_bounds__(256, 2) void text1_tc(const float* __restrict__ b1)
{
    __shared__ uint32_t As[2][4 * ASTR];
    __shared__ uint32_t Bs[2][4 * ASTR];
    int tid = threadIdx.x;
    int lane = tid & 31, wid = tid >> 5;
    int wm = wid & 1, wn = wid >> 1;
    int wrow = wm * 64, wcol = wn * 32;
    int fr = lane >> 2, fc = lane & 3;
    int row0 = blockIdx.y * BM, col0 = blockIdx.x * BN;

    int amM[2], amK[2], bnN[2], bcC[2], aOK[2];
    size_t aBase[2], bOff[2];
    #pragma unroll
    for (int l = 0; l < 2; l++) {
        int idx = tid + l * 256;
        amM[l] = idx >> 2; amK[l] = idx & 3;
        int gr = row0 + amM[l];
        aOK[l] = (gr < MT);
        aBase[l] = (size_t)(aOK[l] ? gr : 0) * K3;
        bnN[l] = idx & 127; bcC[l] = idx >> 7;
        bOff[l] = (size_t)bcC[l] * (HH * 4) + (size_t)(col0 + bnN[l]) * 4;
    }

    const uint4 zero4 = make_uint4(0, 0, 0, 0);
    uint4 aU[2], bU[2];
    #pragma unroll
    for (int l = 0; l < 2; l++) {
        aU[l] = aOK[l] ? *(const uint4*)&g_Xt[aBase[l] + amK[l] * 4] : zero4;
        bU[l] = *(const uint4*)&g_W1T[bOff[l]];
    }

    float acc[4][4][4] = {};
    int p = 0;
    for (int kt = 0; kt < K3; kt += BK) {
        sts_stage_u32(As[p], Bs[p], amM, amK, bnN, bcC, aU, bU);
        __syncthreads();
        int ktn = kt + BK;
        if (ktn < K3) {
            #pragma unroll
            for (int l = 0; l < 2; l++) {
                aU[l] = aOK[l] ? *(const uint4*)&g_Xt[aBase[l] + ktn + amK[l] * 4] : zero4;
                bU[l] = *(const uint4*)&g_W1T[(size_t)(ktn >> 4) * (HH * 16) + bOff[l]];
            }
        }
        mma_stage2(As[p], Bs[p], wrow, wcol, fr, fc, acc);
        p ^= 1;
    }

    #pragma unroll
    for (int mt = 0; mt < 4; mt++) {
        #pragma unroll
        for (int h = 0; h < 2; h++) {
            int r = row0 + wrow + mt * 16 + fr + h * 8;
            if (r >= MT) continue;
            uint32_t* hp = &g_Ht[(size_t)r * HH];
            #pragma unroll
            for (int nt = 0; nt < 4; nt++) {
                int c = col0 + wcol + nt * 8 + fc * 2;
                float x0 = acc[mt][nt][h * 2 + 0] + b1[c];
                float x1 = acc[mt][nt][h * 2 + 1] + b1[c + 1];
                uint2 w = make_uint2(f2tf(fmaxf(x0, 0.f)), f2tf(fmaxf(x1, 0.f)));
                *(uint2*)&hp[c] = w;
            }
        }
    }
}

// ---------------------------------------------------------------------------
// Fused tail (tf32): out[r] = relu(H[r,:]@W2 + b2) @ W3 + b3 (optional mask).
// h_sel: 0 -> g_H1/g_W2gT, 1 -> g_Ht/g_W2tT. A and B both pre-tf32.
// ---------------------------------------------------------------------------
__global__ __launch_bounds__(256, 2) void tail_tc(
    int h_sel, const float* __restrict__ b2, const float* __restrict__ W3,
    const float* __restrict__ b3v, const float* __restrict__ sm,
    const float* __restrict__ im, float* __restrict__ outp,
    int M, int masked)
{
    const uint32_t* Hm = (h_sel == 0) ? g_H1 : g_Ht;
    const uint32_t* W2T = (h_sel == 0) ? g_W2gT : g_W2tT;
    __shared__ uint32_t As[2][4 * ASTR];
    __shared__ uint32_t Bs[2][4 * ASTR];
    __shared__ float red[BM * 16];
    int tid = threadIdx.x;
    int lane = tid & 31, wid = tid >> 5;
    int wm = wid & 1, wn = wid >> 1;
    int wrow = wm * 64, wcol = wn * 32;
    int fr = lane >> 2, fc = lane & 3;
    int row0 = blockIdx.x * BM;
    float rsum[4][2] = {};

    int amM[2], amK[2], bnN[2], bcC[2], aOK[2];
    size_t aBase[2], bCol[2];
    #pragma unroll
    for (int l = 0; l < 2; l++) {
        int idx = tid + l * 256;
        amM[l] = idx >> 2; amK[l] = idx & 3;
        int gr = row0 + amM[l];
        aOK[l] = (gr < M);
        aBase[l] = (size_t)(aOK[l] ? gr : 0) * HH;
        bnN[l] = idx & 127; bcC[l] = idx >> 7;
        bCol[l] = (size_t)bcC[l] * (HH * 4);
    }

    const uint4 zero4 = make_uint4(0, 0, 0, 0);
    int p = 0;
    for (int nc = 0; nc < HH; nc += BN) {
        uint4 aU[2], bU[2];
        #pragma unroll
        for (int l = 0; l < 2; l++) {
            aU[l] = aOK[l] ? *(const uint4*)&Hm[aBase[l] + amK[l] * 4] : zero4;
            bU[l] = *(const uint4*)&W2T[bCol[l] + (size_t)(nc + bnN[l]) * 4];
        }
        float acc[4][4][4] = {};
        for (int kt = 0; kt < HH; kt += BK) {
            sts_stage_u32(As[p], Bs[p], amM, amK, bnN, bcC, aU, bU);
            __syncthreads();
            int ktn = kt + BK;
            if (ktn < HH) {
                #pragma unroll
                for (int l = 0; l < 2; l++) {
                    aU[l] = aOK[l] ? *(const uint4*)&Hm[aBase[l] + ktn + amK[l] * 4] : zero4;
                    bU[l] = *(const uint4*)&W2T[(size_t)(ktn >> 4) * (HH * 16) + bCol[l]
                                                + (size_t)(nc + bnN[l]) * 4];
                }
            }
            mma_stage2(As[p], Bs[p], wrow, wcol, fr, fc, acc);
            p ^= 1;
        }
        #pragma unroll
        for (int mt = 0; mt < 4; mt++) {
            #pragma unroll
            for (int nt = 0; nt < 4; nt++) {
                int c = nc + wcol + nt * 8 + fc * 2;
                float w30 = W3[c], w31 = W3[c + 1];
                float b20 = b2[c], b21 = b2[c + 1];
                rsum[mt][0] += fmaxf(acc[mt][nt][0] + b20, 0.f) * w30
                             + fmaxf(acc[mt][nt][1] + b21, 0.f) * w31;
                rsum[mt][1] += fmaxf(acc[mt][nt][2] + b20, 0.f) * w30
                             + fmaxf(acc[mt][nt][3] + b21, 0.f) * w31;
            }
        }
    }

    #pragma unroll
    for (int mt = 0; mt < 4; mt++)
        #pragma unroll
        for (int h = 0; h < 2; h++) {
            int row = wrow + mt * 16 + fr + h * 8;
            red[row * 16 + wn * 4 + fc] = rsum[mt][h];
        }
    __syncthreads();
    if (tid < BM) {
        int r = row0 + tid;
        if (r < M) {
            float s = 0.f;
            #pragma unroll
            for (int t = 0; t < 16; t++) s += red[tid * 16 + t];
            s += b3v[0];
            if (masked) {
                int gi = r / MJ, gj = r - gi * MJ;
                s *= sm[gi] * im[gj];
            }
            outp[r] = s;
        }
    }
}

// ---------------------------------------------------------------------------
// Small SGEMM (fp32, 64x64 tile) for the two tiny pre-GEMMs f@Wf, v@Ws.
// c_sel: 0 -> g_Apre, 1 -> g_Cpre.
// ---------------------------------------------------------------------------
__global__ __launch_bounds__(256) void sgemm_small(
    const float* __restrict__ A, const float* __restrict__ Bm,
    int c_sel, int M, int N, int K)
{
    float* C = (c_sel == 0) ? g_Apre : g_Cpre;
    __shared__ __align__(16) float As[16][66];
    __shared__ __align__(16) float Bs[16][64];
    int tid = threadIdx.x;
    int tx = tid & 15, ty = tid >> 4;
    int row0 = blockIdx.y * 64, col0 = blockIdx.x * 64;
    float acc[4][4] = {};
    for (int kt = 0; kt < K; kt += 16) {
        #pragma unroll
        for (int l = 0; l < 4; l++) {
            int idx = tid + l * 256;
            int m = idx >> 4, kk = idx & 15;
            int gr = row0 + m;
            As[kk][m] = (gr < M) ? A[(size_t)gr * K + kt + kk] : 0.f;
        }
        #pragma unroll
        for (int l = 0; l < 4; l++) {
            int idx = tid + l * 256;
            int kk = idx >> 6, c = idx & 63;
            Bs[kk][c] = Bm[(size_t)(kt + kk) * N + col0 + c];
        }
        __syncthreads();
        #pragma unroll
        for (int kk = 0; kk < 16; kk++) {
            float av[4];
            #pragma unroll
            for (int i = 0; i < 4; i++) av[i] = As[kk][ty * 4 + i];
            float4 b4 = *(const float4*)&Bs[kk][tx * 4];
            float bv[4] = {b4.x, b4.y, b4.z, b4.w};
            #pragma unroll
            for (int i = 0; i < 4; i++)
                #pragma unroll
                for (int j = 0; j < 4; j++)
                    acc[i][j] += av[i] * bv[j];
        }
        __syncthreads();
    }
    #pragma unroll
    for (int i = 0; i < 4; i++) {
        int r = row0 + ty * 4 + i;
        if (r >= M) continue;
        #pragma unroll
        for (int j = 0; j < 4; j++)
            C[(size_t)r * N + col0 + tx * 4 + j] = acc[i][j];
    }
}

// ---------------------------------------------------------------------------
// Build text concat input (tf32 bits):
// Xt[b*780+p] = [span[fi], span[si], span[fi]*span[si]]
// ---------------------------------------------------------------------------
__global__ void build_xt_kernel(const float* __restrict__ span)
{
    int r = blockIdx.x;
    int b = r / NPAIR, p = r - b * NPAIR;
    int n = 0, rem = p;
    while (rem >= (NS - 1 - n)) { rem -= (NS - 1 - n); n++; }
    int fi = n, si = n + 1 + rem;
    const float* a = span + ((size_t)b * NS + fi) * DD;
    const float* c = span + ((size_t)b * NS + si) * DD;
    uint32_t* x = g_Xt + (size_t)r * K3;
    for (int d = threadIdx.x; d < DD; d += blockDim.x) {
        float av = a[d], cv = c[d];
        x[d] = f2tf(av);
        x[DD + d] = f2tf(cv);
        x[2 * DD + d] = f2tf(av * cv);
    }
}

// ---------------------------------------------------------------------------
// S[8][8] = chunk sums of 800 grounding scores; loss = bidirectional NCE.
// ---------------------------------------------------------------------------
__global__ void loss_kernel(const float* __restrict__ gsc, float* __restrict__ out0)
{
    __shared__ float S[64];
    __shared__ float red[256];
    int tid = threadIdx.x;
    int e = tid >> 2, q = tid & 3;
    float s = 0.f;
    const float* base = gsc + e * 800;
    for (int k = q; k < 800; k += 4) s += base[k];
    red[tid] = s;
    __syncthreads();
    if (q == 0) S[e] = red[tid] + red[tid + 1] + red[tid + 2] + red[tid + 3];
    __syncthreads();
    if (tid == 0) {
        float loss = 0.f;
        for (int a = 0; a < 8; a++) {
            float mx = -1e30f;
            for (int b = 0; b < 8; b++) mx = fmaxf(mx, S[a * 8 + b]);
            float se = 0.f;
            for (int b = 0; b < 8; b++) se += expf(S[a * 8 + b] - mx);
            float lse = mx + logf(se);
            for (int b = 0; b < 8; b++) loss -= (S[a * 8 + b] - lse);
        }
        for (int b = 0; b < 8; b++) {
            float mx = -1e30f;
            for (int a = 0; a < 8; a++) mx = fmaxf(mx, S[a * 8 + b]);
            float se = 0.f;
            for (int a = 0; a < 8; a++) se += expf(S[a * 8 + b] - mx);
            float lse = mx + logf(se);
            for (int a = 0; a < 8; a++) loss -= (S[a * 8 + b] - lse);
        }
        out0[0] = loss / 8.0f;
    }
}

extern "C" void kernel_launch(void* const* d_in, const int* in_sizes, int n_in,
                              void* d_out, int out_size)
{
    const float* span  = (const float*)d_in[0];
    const float* img   = (const float*)d_in[1];
    const float* smask = (const float*)d_in[2];
    const float* imask = (const float*)d_in[3];
    const float* tW1 = (const float*)d_in[4];
    const float* tb1 = (const float*)d_in[5];
    const float* tW2 = (const float*)d_in[6];
    const float* tb2 = (const float*)d_in[7];
    const float* tW3 = (const float*)d_in[8];
    const float* tb3 = (const float*)d_in[9];
    const float* gW1 = (const float*)d_in[10];
    const float* gb1 = (const float*)d_in[11];
    const float* gW2 = (const float*)d_in[12];
    const float* gb2 = (const float*)d_in[13];
    const float* gW3 = (const float*)d_in[14];
    const float* gb3 = (const float*)d_in[15];
    float* out = (float*)d_out;

    dim3 blk(256);

    // Fork a second stream for the independent text path (capture-legal
    // fork/join via events; creation happens only on the 2-3 real calls,
    // graph replays never re-enter kernel_launch).
    cudaStream_t s2;
    cudaStreamCreateWithFlags(&s2, cudaStreamNonBlocking);
    cudaEvent_t evFork, evJoin;
    cudaEventCreateWithFlags(&evFork, cudaEventDisableTiming);
    cudaEventCreateWithFlags(&evJoin, cudaEventDisableTiming);

    cudaEventRecord(evFork, 0);
    cudaStreamWaitEvent(s2, evFork, 0);

    // ---- Text path on s2 ----
    wconv_kernel<<<(K3 * 1024 + 255) / 256, blk, 0, s2>>>(tW1, 1, K3);
    wconv_kernel<<<(HH * 1024 + 255) / 256, blk, 0, s2>>>(tW2, 3, HH);
    build_xt_kernel<<<dim3(MT), blk, 0, s2>>>(span);
    text1_tc<<<dim3(HH / BN, (MT + BM - 1) / BM), blk, 0, s2>>>(tb1);
    tail_tc<<<dim3((MT + BM - 1) / BM), blk, 0, s2>>>(1, tb2, tW3, tb3,
                                                      nullptr, nullptr,
                                                      out + 1 + MG, MT, 0);
    cudaEventRecord(evJoin, s2);

    // ---- Grounding path on the capture (default) stream ----
    wconv_kernel<<<(DD * 1024 + 255) / 256, blk>>>(gW1 + (size_t)2 * DD * HH, 0, DD);
    wconv_kernel<<<(HH * 1024 + 255) / 256, blk>>>(gW2, 2, HH);
    sgemm_small<<<dim3(16, 5), blk>>>(span, gW1, 0, MI, HH, DD);
    sgemm_small<<<dim3(16, 3), blk>>>(img, gW1 + (size_t)DD * HH, 1, MJ, HH, DD);
    ground_h1_tc<<<dim3(HH / BN, MG / BM), blk>>>(span, img, gb1);
    tail_tc<<<dim3(MG / BM), blk>>>(0, gb2, gW3, gb3, smask, imask, out + 1, MG, 1);

    // Join text path back before the final reduction (required for capture
    // legality; loss itself reads only grounding scores).
    cudaStreamWaitEvent(0, evJoin, 0);
    loss_kernel<<<1, 256>>>(out + 1, out);
}

// round 14
// speedup vs baseline: 7.1564x; 1.7714x over previous
#include <cuda_runtime.h>
#include <cuda_fp16.h>
#include <cstdint>

#define DD 1024
#define HH 1024
#define NB 8
#define NS 40
#define NL 20
#define MI 320        // B*N rows of f
#define MJ 160        // B*L rows of v
#define MG 51200      // MI*MJ grounding pairs
#define NPAIR 780     // triu_indices(40, k=1)
#define MT 6240       // B*NPAIR text rows
#define K3 3072

#define BM 128
#define BN 128
#define BK 32         // K per stage (fp16: 16 half2 units)
#define ASTR 520      // plane stride in u32: BM*4 + 8 (conflict-free chunks)

// Scratch (static device globals; no runtime allocation anywhere)
__device__ float    g_Apre[MI * HH];               // f @ Wf (fp32)
__device__ float    g_Cpre[MJ * HH];               // v @ Ws (fp32)
__device__ uint32_t g_H1[(size_t)MG * HH / 2];     // grounding hidden (half2)
__device__ uint32_t g_Xt[(size_t)MT * K3 / 2];     // text concat input (half2)
__device__ uint32_t g_Ht[(size_t)MT * HH / 2];     // text hidden (half2)
// Pre-transformed fp16 weights, tile-plane layout on kk = k/2:
//   WT[((kk/16)*4 + (kk&3)) * (HH*4) + n*4 + ((kk>>2)&3)] = half2(W[2kk][n], W[2kk+1][n])
__device__ uint32_t g_WpT[DD * HH / 2];
__device__ uint32_t g_W1T[(size_t)K3 * HH / 2];
__device__ uint32_t g_W2gT[HH * HH / 2];
__device__ uint32_t g_W2tT[HH * HH / 2];

// ---------------------------------------------------------------------------
// FP16 helpers
// ---------------------------------------------------------------------------
__device__ __forceinline__ uint32_t pack_h2(float lo, float hi) {
    __half2 h = __floats2half2_rn(lo, hi);
    return *(uint32_t*)&h;
}

__device__ __forceinline__ void mma_f16(float* c,
    uint32_t a0, uint32_t a1, uint32_t a2, uint32_t a3,
    uint32_t b0, uint32_t b1)
{
    asm volatile(
        "mma.sync.aligned.m16n8k16.row.col.f32.f16.f16.f32 "
        "{%0,%1,%2,%3}, {%4,%5,%6,%7}, {%8,%9}, {%0,%1,%2,%3};\n"
        : "+f"(c[0]), "+f"(c[1]), "+f"(c[2]), "+f"(c[3])
        : "r"(a0), "r"(a1), "r"(a2), "r"(a3), "r"(b0), "r"(b1));
}

// Weight transform: W[K x 1024] fp32 -> packed-half2 tile-plane layout.
// id = ((tile*4 + q)*1024 + n)*4 + t ; kk = tile*16 + q + 4t ; k0 = 2*kk.
__global__ void wconv_kernel(const float* __restrict__ W, int dst_sel, int K)
{
    uint32_t* out = (dst_sel == 0) ? g_WpT : (dst_sel == 1) ? g_W1T
                  : (dst_sel == 2) ? g_W2gT : g_W2tT;
    int id = blockIdx.x * 256 + threadIdx.x;
    if (id >= K * 512) return;
    int t = id & 3, n = (id >> 2) & 1023;
    int q = (id >> 12) & 3, tile = id >> 14;
    int k0 = 2 * (tile * 16 + q + 4 * t);
    out[id] = pack_h2(W[(size_t)k0 * 1024 + n], W[(size_t)(k0 + 1) * 1024 + n]);
}

// Smem layout (on kk = k/2): element (kk, x) at plane (kk&3), offset x*4 + (kk>>2).
// One uint4 at plane fc, offset x*4 yields kk = fc, fc+4, fc+8, fc+12 — the A/B
// fragments of BOTH m16n8k16 MMAs (k 0-15 via .x/.y, k 16-31 via .z/.w).
__device__ __forceinline__ void mma_stage_f16(
    const uint32_t* __restrict__ Asb, const uint32_t* __restrict__ Bsb,
    int wrow, int wcol, int fr, int fc, float acc[4][4][4])
{
    const uint32_t* ab = Asb + fc * ASTR;
    const uint32_t* bb = Bsb + fc * ASTR;
    uint4 alo[4], ahi[4];
    #pragma unroll
    for (int mt = 0; mt < 4; mt++) {
        int m = wrow + mt * 16 + fr;
        alo[mt] = *(const uint4*)&ab[m * 4];
        ahi[mt] = *(const uint4*)&ab[(m + 8) * 4];
    }
    #pragma unroll
    for (int nt = 0; nt < 4; nt++) {
        int n = wcol + nt * 8 + fr;
        uint4 bq = *(const uint4*)&bb[n * 4];
        #pragma unroll
        for (int mt = 0; mt < 4; mt++) {
            mma_f16(acc[mt][nt], alo[mt].x, ahi[mt].x, alo[mt].y, ahi[mt].y, bq.x, bq.y);
            mma_f16(acc[mt][nt], alo[mt].z, ahi[mt].z, alo[mt].w, ahi[mt].w, bq.z, bq.w);
        }
    }
}

// Staging stores. A slot (m, kq): 4 STS.32 to planes 0-3 (kk = 4kq+q).
// B slot (n, plane c): 1 STS.128 (kk = c + 4t).
__device__ __forceinline__ void sts_stage_u32(
    uint32_t* Asb, uint32_t* Bsb,
    const int* amM, const int* amK, const int* bnN, const int* bcC,
    const uint4* aU, const uint4* bU)
{
    #pragma unroll
    for (int l = 0; l < 2; l++) {
        Asb[0 * ASTR + amM[l] * 4 + amK[l]] = aU[l].x;
        Asb[1 * ASTR + amM[l] * 4 + amK[l]] = aU[l].y;
        Asb[2 * ASTR + amM[l] * 4 + amK[l]] = aU[l].z;
        Asb[3 * ASTR + amM[l] * 4 + amK[l]] = aU[l].w;
        *(uint4*)&Bsb[bcC[l] * ASTR + bnN[l] * 4] = bU[l];
    }
}

// ---------------------------------------------------------------------------
// Grounding layer 1 (fused A-gen, fp16 tensor cores):
// H1[r,c] = relu((f_i⊙v_j)@Wp + Apre[i,c] + Cpre[j,c] + b1[c]), r = i*160+j.
// ---------------------------------------------------------------------------
__global__ __launch_bounds__(256, 2) void ground_h1_tc(
    const float* __restrict__ f, const float* __restrict__ v,
    const float* __restrict__ b1)
{
    __shared__ uint32_t As[2][4 * ASTR];
    __shared__ uint32_t Bs[2][4 * ASTR];
    int tid = threadIdx.x;
    int lane = tid & 31, wid = tid >> 5;
    int wm = wid & 1, wn = wid >> 1;
    int wrow = wm * 64, wcol = wn * 32;
    int fr = lane >> 2, fc = lane & 3;
    int row0 = blockIdx.y * BM, col0 = blockIdx.x * BN;

    int amM[2], amK[2], bnN[2], bcC[2];
    size_t aF[2], aV[2], bOff[2];
    #pragma unroll
    for (int l = 0; l < 2; l++) {
        int idx = tid + l * 256;
        amM[l] = idx >> 2; amK[l] = idx & 3;
        int gr = row0 + amM[l];
        int gi = gr / MJ, gj = gr - gi * MJ;
        aF[l] = (size_t)gi * DD; aV[l] = (size_t)gj * DD;
        bnN[l] = idx & 127; bcC[l] = idx >> 7;
        bOff[l] = (size_t)bcC[l] * (HH * 4) + (size_t)(col0 + bnN[l]) * 4;
    }

    uint4 aU[2], bU[2];
    #pragma unroll
    for (int l = 0; l < 2; l++) {
        size_t ka = amK[l] * 8;
        float4 fa = *(const float4*)&f[aF[l] + ka];
        float4 fb = *(const float4*)&f[aF[l] + ka + 4];
        float4 va = *(const float4*)&v[aV[l] + ka];
        float4 vb = *(const float4*)&v[aV[l] + ka + 4];
        aU[l] = make_uint4(pack_h2(fa.x * va.x, fa.y * va.y),
                           pack_h2(fa.z * va.z, fa.w * va.w),
                           pack_h2(fb.x * vb.x, fb.y * vb.y),
                           pack_h2(fb.z * vb.z, fb.w * vb.w));
        bU[l] = *(const uint4*)&g_WpT[bOff[l]];
    }

    float acc[4][4][4] = {};
    int p = 0;
    for (int kt = 0; kt < DD; kt += BK) {
        sts_stage_u32(As[p], Bs[p], amM, amK, bnN, bcC, aU, bU);
        __syncthreads();
        int ktn = kt + BK;
        if (ktn < DD) {
            #pragma unroll
            for (int l = 0; l < 2; l++) {
                size_t ka = ktn + amK[l] * 8;
                float4 fa = *(const float4*)&f[aF[l] + ka];
                float4 fb = *(const float4*)&f[aF[l] + ka + 4];
                float4 va = *(const float4*)&v[aV[l] + ka];
                float4 vb = *(const float4*)&v[aV[l] + ka + 4];
                aU[l] = make_uint4(pack_h2(fa.x * va.x, fa.y * va.y),
                                   pack_h2(fa.z * va.z, fa.w * va.w),
                                   pack_h2(fb.x * vb.x, fb.y * vb.y),
                                   pack_h2(fb.z * vb.z, fb.w * vb.w));
                bU[l] = *(const uint4*)&g_WpT[(size_t)(ktn >> 5) * (HH * 16) + bOff[l]];
            }
        }
        mma_stage_f16(As[p], Bs[p], wrow, wcol, fr, fc, acc);
        p ^= 1;
    }

    #pragma unroll
    for (int mt = 0; mt < 4; mt++) {
        #pragma unroll
        for (int h = 0; h < 2; h++) {
            int r = row0 + wrow + mt * 16 + fr + h * 8;
            int gi = r / MJ, gj = r - gi * MJ;
            const float* ap = &g_Apre[(size_t)gi * HH];
            const float* cp = &g_Cpre[(size_t)gj * HH];
            uint32_t* hp = &g_H1[(size_t)r * (HH / 2)];
            #pragma unroll
            for (int nt = 0; nt < 4; nt++) {
                int c = col0 + wcol + nt * 8 + fc * 2;
                float x0 = acc[mt][nt][h * 2 + 0] + ap[c] + cp[c] + b1[c];
                float x1 = acc[mt][nt][h * 2 + 1] + ap[c + 1] + cp[c + 1] + b1[c + 1];
                hp[c >> 1] = pack_h2(fmaxf(x0, 0.f), fmaxf(x1, 0.f));
            }
        }
    }
}

// ---------------------------------------------------------------------------
// Text layer 1: g_Ht = relu(g_Xt @ tW1 + tb1). A packed-half2, B pre-transformed.
// ---------------------------------------------------------------------------
__global__ __launch_bounds__(256, 2) void text1_tc(const float* __restrict__ b1)
{
    __shared__ uint32_t As[2][4 * ASTR];
    __shared__ uint32_t Bs[2][4 * ASTR];
    int tid = threadIdx.x;
    int lane = tid & 31, wid = tid >> 5;
    int wm = wid & 1, wn = wid >> 1;
    int wrow = wm * 64, wcol = wn * 32;
    int fr = lane >> 2, fc = lane & 3;
    int row0 = blockIdx.y * BM, col0 = blockIdx.x * BN;

    int amM[2], amK[2], bnN[2], bcC[2], aOK[2];
    size_t aBase[2], bOff[2];
    #pragma unroll
    for (int l = 0; l < 2; l++) {
        int idx = tid + l * 256;
        amM[l] = idx >> 2; amK[l] = idx & 3;
        int gr = row0 + amM[l];
        aOK[l] = (gr < MT);
        aBase[l] = (size_t)(aOK[l] ? gr : 0) * (K3 / 2);
        bnN[l] = idx & 127; bcC[l] = idx >> 7;
        bOff[l] = (size_t)bcC[l] * (HH * 4) + (size_t)(col0 + bnN[l]) * 4;
    }

    const uint4 zero4 = make_uint4(0, 0, 0, 0);
    uint4 aU[2], bU[2];
    #pragma unroll
    for (int l = 0; l < 2; l++) {
        aU[l] = aOK[l] ? *(const uint4*)&g_Xt[aBase[l] + amK[l] * 4] : zero4;
        bU[l] = *(const uint4*)&g_W1T[bOff[l]];
    }

    float acc[4][4][4] = {};
    int p = 0;
    for (int kt = 0; kt < K3; kt += BK) {
        sts_stage_u32(As[p], Bs[p], amM, amK, bnN, bcC, aU, bU);
        __syncthreads();
        int ktn = kt + BK;
        if (ktn < K3) {
            #pragma unroll
            for (int l = 0; l < 2; l++) {
                aU[l] = aOK[l] ? *(const uint4*)&g_Xt[aBase[l] + (ktn >> 1) + amK[l] * 4] : zero4;
                bU[l] = *(const uint4*)&g_W1T[(size_t)(ktn >> 5) * (HH * 16) + bOff[l]];
            }
        }
        mma_stage_f16(As[p], Bs[p], wrow, wcol, fr, fc, acc);
        p ^= 1;
    }

    #pragma unroll
    for (int mt = 0; mt < 4; mt++) {
        #pragma unroll
        for (int h = 0; h < 2; h++) {
            int r = row0 + wrow + mt * 16 + fr + h * 8;
            if (r >= MT) continue;
            uint32_t* hp = &g_Ht[(size_t)r * (HH / 2)];
            #pragma unroll
            for (int nt = 0; nt < 4; nt++) {
                int c = col0 + wcol + nt * 8 + fc * 2;
                float x0 = acc[mt][nt][h * 2 + 0] + b1[c];
                float x1 = acc[mt][nt][h * 2 + 1] + b1[c + 1];
                hp[c >> 1] = pack_h2(fmaxf(x0, 0.f), fmaxf(x1, 0.f));
            }
        }
    }
}

// ---------------------------------------------------------------------------
// Fused tail (fp16): out[r] = relu(H[r,:]@W2 + b2) @ W3 + b3 (optional mask).
// h_sel: 0 -> g_H1/g_W2gT, 1 -> g_Ht/g_W2tT.
// ---------------------------------------------------------------------------
__global__ __launch_bounds__(256, 2) void tail_tc(
    int h_sel, const float* __restrict__ b2, const float* __restrict__ W3,
    const float* __restrict__ b3v, const float* __restrict__ sm,
    const float* __restrict__ im, float* __restrict__ outp,
    int M, int masked)
{
    const uint32_t* Hm = (h_sel == 0) ? g_H1 : g_Ht;
    const uint32_t* W2T = (h_sel == 0) ? g_W2gT : g_W2tT;
    __shared__ uint32_t As[2][4 * ASTR];
    __shared__ uint32_t Bs[2][4 * ASTR];
    __shared__ float red[BM * 16];
    int tid = threadIdx.x;
    int lane = tid & 31, wid = tid >> 5;
    int wm = wid & 1, wn = wid >> 1;
    int wrow = wm * 64, wcol = wn * 32;
    int fr = lane >> 2, fc = lane & 3;
    int row0 = blockIdx.x * BM;
    float rsum[4][2] = {};

    int amM[2], amK[2], bnN[2], bcC[2], aOK[2];
    size_t aBase[2], bCol[2];
    #pragma unroll
    for (int l = 0; l < 2; l++) {
        int idx = tid + l * 256;
        amM[l] = idx >> 2; amK[l] = idx & 3;
        int gr = row0 + amM[l];
        aOK[l] = (gr < M);
        aBase[l] = (size_t)(aOK[l] ? gr : 0) * (HH / 2);
        bnN[l] = idx & 127; bcC[l] = idx >> 7;
        bCol[l] = (size_t)bcC[l] * (HH * 4);
    }

    const uint4 zero4 = make_uint4(0, 0, 0, 0);
    int p = 0;
    for (int nc = 0; nc < HH; nc += BN) {
        uint4 aU[2], bU[2];
        #pragma unroll
        for (int l = 0; l < 2; l++) {
            aU[l] = aOK[l] ? *(const uint4*)&Hm[aBase[l] + amK[l] * 4] : zero4;
            bU[l] = *(const uint4*)&W2T[bCol[l] + (size_t)(nc + bnN[l]) * 4];
        }
        float acc[4][4][4] = {};
        for (int kt = 0; kt < HH; kt += BK) {
            sts_stage_u32(As[p], Bs[p], amM, amK, bnN, bcC, aU, bU);
            __syncthreads();
            int ktn = kt + BK;
            if (ktn < HH) {
                #pragma unroll
                for (int l = 0; l < 2; l++) {
                    aU[l] = aOK[l] ? *(const uint4*)&Hm[aBase[l] + (ktn >> 1) + amK[l] * 4] : zero4;
                    bU[l] = *(const uint4*)&W2T[(size_t)(ktn >> 5) * (HH * 16) + bCol[l]
                                                + (size_t)(nc + bnN[l]) * 4];
                }
            }
            mma_stage_f16(As[p], Bs[p], wrow, wcol, fr, fc, acc);
            p ^= 1;
        }
        #pragma unroll
        for (int mt = 0; mt < 4; mt++) {
            #pragma unroll
            for (int nt = 0; nt < 4; nt++) {
                int c = nc + wcol + nt * 8 + fc * 2;
                float w30 = W3[c], w31 = W3[c + 1];
                float b20 = b2[c], b21 = b2[c + 1];
                rsum[mt][0] += fmaxf(acc[mt][nt][0] + b20, 0.f) * w30
                             + fmaxf(acc[mt][nt][1] + b21, 0.f) * w31;
                rsum[mt][1] += fmaxf(acc[mt][nt][2] + b20, 0.f) * w30
                             + fmaxf(acc[mt][nt][3] + b21, 0.f) * w31;
            }
        }
    }

    #pragma unroll
    for (int mt = 0; mt < 4; mt++)
        #pragma unroll
        for (int h = 0; h < 2; h++) {
            int row = wrow + mt * 16 + fr + h * 8;
            red[row * 16 + wn * 4 + fc] = rsum[mt][h];
        }
    __syncthreads();
    if (tid < BM) {
        int r = row0 + tid;
        if (r < M) {
            float s = 0.f;
            #pragma unroll
            for (int t = 0; t < 16; t++) s += red[tid * 16 + t];
            s += b3v[0];
            if (masked) {
                int gi = r / MJ, gj = r - gi * MJ;
                s *= sm[gi] * im[gj];
            }
            outp[r] = s;
        }
    }
}

// ---------------------------------------------------------------------------
// Small SGEMM (fp32, 64x64 tile) for the two tiny pre-GEMMs f@Wf, v@Ws.
// ---------------------------------------------------------------------------
__global__ __launch_bounds__(256) void sgemm_small(
    const float* __restrict__ A, const float* __restrict__ Bm,
    int c_sel, int M, int N, int K)
{
    float* C = (c_sel == 0) ? g_Apre : g_Cpre;
    __shared__ __align__(16) float As[16][66];
    __shared__ __align__(16) float Bs[16][64];
    int tid = threadIdx.x;
    int tx = tid & 15, ty = tid >> 4;
    int row0 = blockIdx.y * 64, col0 = blockIdx.x * 64;
    float acc[4][4] = {};
    for (int kt = 0; kt < K; kt += 16) {
        #pragma unroll
        for (int l = 0; l < 4; l++) {
            int idx = tid + l * 256;
            int m = idx >> 4, kk = idx & 15;
            int gr = row0 + m;
            As[kk][m] = (gr < M) ? A[(size_t)gr * K + kt + kk] : 0.f;
        }
        #pragma unroll
        for (int l = 0; l < 4; l++) {
            int idx = tid + l * 256;
            int kk = idx >> 6, c = idx & 63;
            Bs[kk][c] = Bm[(size_t)(kt + kk) * N + col0 + c];
        }
        __syncthreads();
        #pragma unroll
        for (int kk = 0; kk < 16; kk++) {
            float av[4];
            #pragma unroll
            for (int i = 0; i < 4; i++) av[i] = As[kk][ty * 4 + i];
            float4 b4 = *(const float4*)&Bs[kk][tx * 4];
            float bv[4] = {b4.x, b4.y, b4.z, b4.w};
            #pragma unroll
            for (int i = 0; i < 4; i++)
                #pragma unroll
                for (int j = 0; j < 4; j++)
                    acc[i][j] += av[i] * bv[j];
        }
        __syncthreads();
    }
    #pragma unroll
    for (int i = 0; i < 4; i++) {
        int r = row0 + ty * 4 + i;
        if (r >= M) continue;
        #pragma unroll
        for (int j = 0; j < 4; j++)
            C[(size_t)r * N + col0 + tx * 4 + j] = acc[i][j];
    }
}

// ---------------------------------------------------------------------------
// Build text concat input (packed half2):
// Xt[b*780+p] = [span[fi], span[si], span[fi]*span[si]]
// ---------------------------------------------------------------------------
__global__ void build_xt_kernel(const float* __restrict__ span)
{
    int r = blockIdx.x;
    int b = r / NPAIR, p = r - b * NPAIR;
    int n = 0, rem = p;
    while (rem >= (NS - 1 - n)) { rem -= (NS - 1 - n); n++; }
    int fi = n, si = n + 1 + rem;
    const float2* a2 = (const float2*)(span + ((size_t)b * NS + fi) * DD);
    const float2* c2 = (const float2*)(span + ((size_t)b * NS + si) * DD);
    uint32_t* x = g_Xt + (size_t)r * (K3 / 2);
    for (int d = threadIdx.x; d < DD / 2; d += blockDim.x) {
        float2 aa = a2[d], cc = c2[d];
        x[d] = pack_h2(aa.x, aa.y);
        x[DD / 2 + d] = pack_h2(cc.x, cc.y);
        x[DD + d] = pack_h2(aa.x * cc.x, aa.y * cc.y);
    }
}

// ---------------------------------------------------------------------------
// S[8][8] = chunk sums of 800 grounding scores; loss = bidirectional NCE.
// ---------------------------------------------------------------------------
__global__ void loss_kernel(const float* __restrict__ gsc, float* __restrict__ out0)
{
    __shared__ float S[64];
    __shared__ float red[256];
    int tid = threadIdx.x;
    int e = tid >> 2, q = tid & 3;
    float s = 0.f;
    const float* base = gsc + e * 800;
    for (int k = q; k < 800; k += 4) s += base[k];
    red[tid] = s;
    __syncthreads();
    if (q == 0) S[e] = red[tid] + red[tid + 1] + red[tid + 2] + red[tid + 3];
    __syncthreads();
    if (tid == 0) {
        float loss = 0.f;
        for (int a = 0; a < 8; a++) {
            float mx = -1e30f;
            for (int b = 0; b < 8; b++) mx = fmaxf(mx, S[a * 8 + b]);
            float se = 0.f;
            for (int b = 0; b < 8; b++) se += expf(S[a * 8 + b] - mx);
            float lse = mx + logf(se);
            for (int b = 0; b < 8; b++) loss -= (S[a * 8 + b] - lse);
        }
        for (int b = 0; b < 8; b++) {
            float mx = -1e30f;
            for (int a = 0; a < 8; a++) mx = fmaxf(mx, S[a * 8 + b]);
            float se = 0.f;
            for (int a = 0; a < 8; a++) se += expf(S[a * 8 + b] - mx);
            float lse = mx + logf(se);
            for (int a = 0; a < 8; a++) loss -= (S[a * 8 + b] - lse);
        }
        out0[0] = loss / 8.0f;
    }
}

extern "C" void kernel_launch(void* const* d_in, const int* in_sizes, int n_in,
                              void* d_out, int out_size)
{
    const float* span  = (const float*)d_in[0];
    const float* img   = (const float*)d_in[1];
    const float* smask = (const float*)d_in[2];
    const float* imask = (const float*)d_in[3];
    const float* tW1 = (const float*)d_in[4];
    const float* tb1 = (const float*)d_in[5];
    const float* tW2 = (const float*)d_in[6];
    const float* tb2 = (const float*)d_in[7];
    const float* tW3 = (const float*)d_in[8];
    const float* tb3 = (const float*)d_in[9];
    const float* gW1 = (const float*)d_in[10];
    const float* gb1 = (const float*)d_in[11];
    const float* gW2 = (const float*)d_in[12];
    const float* gb2 = (const float*)d_in[13];
    const float* gW3 = (const float*)d_in[14];
    const float* gb3 = (const float*)d_in[15];
    float* out = (float*)d_out;

    dim3 blk(256);

    // Fork a second stream for the independent text path (capture-legal
    // fork/join via events).
    cudaStream_t s2;
    cudaStreamCreateWithFlags(&s2, cudaStreamNonBlocking);
    cudaEvent_t evFork, evJoin;
    cudaEventCreateWithFlags(&evFork, cudaEventDisableTiming);
    cudaEventCreateWithFlags(&evJoin, cudaEventDisableTiming);

    cudaEventRecord(evFork, 0);
    cudaStreamWaitEvent(s2, evFork, 0);

    // ---- Text path on s2 ----
    wconv_kernel<<<(K3 * 512 + 255) / 256, blk, 0, s2>>>(tW1, 1, K3);
    wconv_kernel<<<(HH * 512 + 255) / 256, blk, 0, s2>>>(tW2, 3, HH);
    build_xt_kernel<<<dim3(MT), blk, 0, s2>>>(span);
    text1_tc<<<dim3(HH / BN, (MT + BM - 1) / BM), blk, 0, s2>>>(tb1);
    tail_tc<<<dim3((MT + BM - 1) / BM), blk, 0, s2>>>(1, tb2, tW3, tb3,
                                                      nullptr, nullptr,
                                                      out + 1 + MG, MT, 0);
    cudaEventRecord(evJoin, s2);

    // ---- Grounding path on the capture (default) stream ----
    wconv_kernel<<<(DD * 512 + 255) / 256, blk>>>(gW1 + (size_t)2 * DD * HH, 0, DD);
    wconv_kernel<<<(HH * 512 + 255) / 256, blk>>>(gW2, 2, HH);
    sgemm_small<<<dim3(16, 5), blk>>>(span, gW1, 0, MI, HH, DD);
    sgemm_small<<<dim3(16, 3), blk>>>(img, gW1 + (size_t)DD * HH, 1, MJ, HH, DD);
    ground_h1_tc<<<dim3(HH / BN, MG / BM), blk>>>(span, img, gb1);
    tail_tc<<<dim3(MG / BM), blk>>>(0, gb2, gW3, gb3, smask, imask, out + 1, MG, 1);

    // Join text path before the final reduction.
    cudaStreamWaitEvent(0, evJoin, 0);
    loss_kernel<<<1, 256>>>(out + 1, out);
}